// round 2
// baseline (speedup 1.0000x reference)
#include <cuda_runtime.h>
#include <cstdint>
#include <math.h>

#define PATHS 4096
#define LEN 8
#define DIM 256
#define HID 256
#define NG 1024   // 4*HID
#define KDIM 256

#define BM 128
#define BN 128
#define BK 32
#define ASTRIDE 36                       // 36 % 32 == 4 -> conflict-free frag loads
#define STAGEF ((BM + BN) * ASTRIDE)     // floats per pipeline stage
#define SMEM_BYTES (2 * STAGEF * 4)      // 73728 bytes

// ---------------- device scratch (static allocation is allowed) ----------------
__device__ float g_Gin[(size_t)LEN * PATHS * NG];   // 128 MB: precomputed input gates (permuted cols)
__device__ float g_Wih[NG * KDIM];                  // permuted w_ih  (row 4j+q)
__device__ float g_Whh[NG * KDIM];                  // permuted w_hh
__device__ float g_bias[NG];                        // permuted b_ih+b_hh
__device__ float g_hbuf[2][PATHS * HID];
__device__ float g_cbuf[PATHS * HID];
__device__ float g_att[PATHS];
__device__ float g_pe[HID];

// ---------------- helpers ----------------
__device__ __forceinline__ void cp16(void* smem_dst, const void* gmem_src) {
    uint32_t s = (uint32_t)__cvta_generic_to_shared(smem_dst);
    asm volatile("cp.async.cg.shared.global [%0], [%1], 16;\n" :: "r"(s), "l"(gmem_src));
}
__device__ __forceinline__ void cp_commit() { asm volatile("cp.async.commit_group;\n"); }
__device__ __forceinline__ void cp_wait0()  { asm volatile("cp.async.wait_group 0;\n"); }

__device__ __forceinline__ void mma_tf32(float* c, const uint32_t* a, const uint32_t* b) {
    asm volatile(
        "mma.sync.aligned.m16n8k8.row.col.f32.tf32.tf32.f32 "
        "{%0,%1,%2,%3},{%4,%5,%6,%7},{%8,%9},{%0,%1,%2,%3};\n"
        : "+f"(c[0]), "+f"(c[1]), "+f"(c[2]), "+f"(c[3])
        : "r"(a[0]), "r"(a[1]), "r"(a[2]), "r"(a[3]), "r"(b[0]), "r"(b[1]));
}

__device__ __forceinline__ float sigf(float x) { return 1.0f / (1.0f + __expf(-x)); }

// ---------------- weight permutation: row 4j+q <- row q*HID+j ----------------
__global__ void prep_kernel(const float* __restrict__ w_ih, const float* __restrict__ w_hh,
                            const float* __restrict__ b_ih, const float* __restrict__ b_hh) {
    int idx = blockIdx.x * blockDim.x + threadIdx.x;   // over NG*KDIM
    if (idx < NG * KDIM) {
        int r = idx >> 8;        // output row (0..1023)
        int k = idx & 255;
        int j = r >> 2, q = r & 3;
        int src = (q * HID + j) * KDIM + k;
        g_Wih[idx] = w_ih[src];
        g_Whh[idx] = w_hh[src];
        if (k == 0) g_bias[r] = b_ih[q * HID + j] + b_hh[q * HID + j];
    }
}

// ---------------- unified tf32 GEMM ----------------
// MODE 0: Gin[m][n] = gather(embedding,paths)[m] @ Wih^T + bias     (m = t*PATHS + p)
// MODE 1: gates = Gin[t] + h_in @ Whh^T ; fused LSTM cell epilogue
template <int MODE>
__global__ void __launch_bounds__(256)
gemm_kernel(const float* __restrict__ emb, const int* __restrict__ paths, int t) {
    extern __shared__ float smem[];
    const int tid = threadIdx.x;
    const int m0 = blockIdx.y * BM;
    const int n0 = blockIdx.x * BN;

    const float* __restrict__ Bsrc = (MODE == 0) ? g_Wih : g_Whh;
    const float* hin = (MODE == 1) ? g_hbuf[(t + 1) & 1] : nullptr;

    // global->smem copy plan: 2 threads per row, 16 floats each (4x cp.async 16B)
    const int arow = tid >> 1;
    const int aoff = (tid & 1) * 16;
    const float* aptr;
    if (MODE == 0) {
        int m = m0 + arow;
        int tt = m >> 12;            // m = t*4096 + p
        int p = m & 4095;
        int ridx = paths[p * LEN + tt];
        aptr = emb + (size_t)ridx * DIM + aoff;
    } else {
        aptr = hin + (m0 + arow) * KDIM + aoff;
    }
    const float* bptr = Bsrc + (n0 + arow) * KDIM + aoff;

    const int warp = tid >> 5, lane = tid & 31;
    const int wm = warp >> 1, wn = warp & 1;       // 4x2 warp grid, warp tile 32x64
    const int g = lane >> 2, t4 = lane & 3;

    float acc[2][8][4];
    #pragma unroll
    for (int a = 0; a < 2; a++)
        #pragma unroll
        for (int b = 0; b < 8; b++)
            #pragma unroll
            for (int c = 0; c < 4; c++) acc[a][b][c] = 0.0f;

    // issue stage 0
    {
        float* sa = smem + arow * ASTRIDE + aoff;
        float* sb = smem + BM * ASTRIDE + arow * ASTRIDE + aoff;
        #pragma unroll
        for (int i = 0; i < 4; i++) { cp16(sa + i * 4, aptr + i * 4); cp16(sb + i * 4, bptr + i * 4); }
        cp_commit();
    }

    #pragma unroll
    for (int kc = 0; kc < KDIM / BK; kc++) {
        cp_wait0();
        __syncthreads();
        if (kc + 1 < KDIM / BK) {
            float* base = smem + ((kc + 1) & 1) * STAGEF;
            float* sa = base + arow * ASTRIDE + aoff;
            float* sb = base + BM * ASTRIDE + arow * ASTRIDE + aoff;
            const float* ga = aptr + (kc + 1) * BK;
            const float* gb = bptr + (kc + 1) * BK;
            #pragma unroll
            for (int i = 0; i < 4; i++) { cp16(sa + i * 4, ga + i * 4); cp16(sb + i * 4, gb + i * 4); }
            cp_commit();
        }
        const uint32_t* Au = (const uint32_t*)(smem + (kc & 1) * STAGEF);
        const uint32_t* Bu = Au + BM * ASTRIDE;

        #pragma unroll
        for (int ks = 0; ks < 4; ks++) {
            const int kb = ks * 8;
            uint32_t afr[2][4], bfr[8][2];
            #pragma unroll
            for (int mt = 0; mt < 2; mt++) {
                int rb = wm * 32 + mt * 16;
                afr[mt][0] = Au[(rb + g) * ASTRIDE + kb + t4];
                afr[mt][1] = Au[(rb + g + 8) * ASTRIDE + kb + t4];
                afr[mt][2] = Au[(rb + g) * ASTRIDE + kb + t4 + 4];
                afr[mt][3] = Au[(rb + g + 8) * ASTRIDE + kb + t4 + 4];
            }
            #pragma unroll
            for (int nt = 0; nt < 8; nt++) {
                int cb = wn * 64 + nt * 8;
                bfr[nt][0] = Bu[(cb + g) * ASTRIDE + kb + t4];
                bfr[nt][1] = Bu[(cb + g) * ASTRIDE + kb + t4 + 4];
            }
            #pragma unroll
            for (int mt = 0; mt < 2; mt++)
                #pragma unroll
                for (int nt = 0; nt < 8; nt++) mma_tf32(acc[mt][nt], afr[mt], bfr[nt]);
        }
    }

    if (MODE == 0) {
        // epilogue: add bias, write Gin
        #pragma unroll
        for (int mt = 0; mt < 2; mt++) {
            #pragma unroll
            for (int nt = 0; nt < 8; nt++) {
                int row = m0 + wm * 32 + mt * 16 + g;
                int col = n0 + wn * 64 + nt * 8 + 2 * t4;
                float b0 = g_bias[col], b1 = g_bias[col + 1];
                float2 v0 = make_float2(acc[mt][nt][0] + b0, acc[mt][nt][1] + b1);
                float2 v1 = make_float2(acc[mt][nt][2] + b0, acc[mt][nt][3] + b1);
                *(float2*)&g_Gin[(size_t)row * NG + col] = v0;
                *(float2*)&g_Gin[(size_t)(row + 8) * NG + col] = v1;
            }
        }
    } else {
        // fused LSTM cell epilogue: stage 64-row halves of the gate tile in smem
        const size_t ginbase = (size_t)(t * PATHS + m0) * NG;
        float* hout = g_hbuf[t & 1];
        float* sg = smem;   // 64*128 floats = 32KB, reuses pipeline smem
        #pragma unroll
        for (int half = 0; half < 2; half++) {
            __syncthreads();
            if ((wm >> 1) == half) {
                #pragma unroll
                for (int mt = 0; mt < 2; mt++) {
                    #pragma unroll
                    for (int nt = 0; nt < 8; nt++) {
                        int lr = (wm & 1) * 32 + mt * 16 + g;       // 0..63 within half
                        int col = wn * 64 + nt * 8 + 2 * t4;        // 0..127 within tile
                        int grow = half * 64 + lr;                  // 0..127 within block
                        const float* gin = &g_Gin[ginbase + (size_t)grow * NG + (n0 + col)];
                        sg[lr * 128 + col]           = acc[mt][nt][0] + gin[0];
                        sg[lr * 128 + col + 1]       = acc[mt][nt][1] + gin[1];
                        sg[(lr + 8) * 128 + col]     = acc[mt][nt][2] + gin[8 * NG];
                        sg[(lr + 8) * 128 + col + 1] = acc[mt][nt][3] + gin[8 * NG + 1];
                    }
                }
            }
            __syncthreads();
            // cell update: 64 rows x 32 hidden units = 2048 cells, 8 per thread
            #pragma unroll
            for (int i = 0; i < 8; i++) {
                int idx = tid + i * 256;
                int lr = idx >> 5, j = idx & 31;
                float4 gv = *(const float4*)(sg + lr * 128 + j * 4);
                int grow = m0 + half * 64 + lr;
                int jg = (n0 >> 2) + j;
                float ig = sigf(gv.x);
                float fg = sigf(gv.y);
                float gg = tanhf(gv.z);
                float og = sigf(gv.w);
                int ci = grow * HID + jg;
                float c = g_cbuf[ci];
                c = fg * c + ig * gg;
                g_cbuf[ci] = c;
                hout[ci] = og * tanhf(c);
            }
        }
    }
}

// ---------------- step 0: h=c=0 -> cell update straight from Gin[0] ----------------
__global__ void step0_kernel() {
    int idx = blockIdx.x * blockDim.x + threadIdx.x;   // PATHS*HID
    float4 gv = *(const float4*)&g_Gin[(size_t)idx * 4];   // row p = idx>>8, 4j = (idx&255)*4 contiguous
    float ig = sigf(gv.x);
    float fg = sigf(gv.y); (void)fg;                    // c_old = 0
    float gg = tanhf(gv.z);
    float og = sigf(gv.w);
    float c = ig * gg;
    g_cbuf[idx] = c;
    g_hbuf[0][idx] = og * tanhf(c);
}

// ---------------- attention logit: max over hidden ----------------
__global__ void att_kernel() {
    int warp = threadIdx.x >> 5, lane = threadIdx.x & 31;
    int p = blockIdx.x * 8 + warp;
    const float* h = g_hbuf[1] + p * HID;
    float m = -1e30f;
    #pragma unroll
    for (int k = lane; k < HID; k += 32) m = fmaxf(m, h[k]);
    #pragma unroll
    for (int o = 16; o; o >>= 1) m = fmaxf(m, __shfl_xor_sync(0xffffffffu, m, o));
    if (lane == 0) g_att[p] = m;
}

// ---------------- softmax over 4096 paths (single block) ----------------
__global__ void softmax_kernel() {
    __shared__ float red[32];
    __shared__ float bval;
    int tid = threadIdx.x;        // 1024 threads
    float l[4];
    float m = -1e30f;
    #pragma unroll
    for (int i = 0; i < 4; i++) { l[i] = g_att[tid * 4 + i]; m = fmaxf(m, l[i]); }
    #pragma unroll
    for (int o = 16; o; o >>= 1) m = fmaxf(m, __shfl_xor_sync(0xffffffffu, m, o));
    if ((tid & 31) == 0) red[tid >> 5] = m;
    __syncthreads();
    if (tid < 32) {
        float v = red[tid];
        #pragma unroll
        for (int o = 16; o; o >>= 1) v = fmaxf(v, __shfl_xor_sync(0xffffffffu, v, o));
        if (tid == 0) bval = v;
    }
    __syncthreads();
    float M = bval;
    float e[4], s = 0.0f;
    #pragma unroll
    for (int i = 0; i < 4; i++) { e[i] = expf(l[i] - M); s += e[i]; }
    #pragma unroll
    for (int o = 16; o; o >>= 1) s += __shfl_xor_sync(0xffffffffu, s, o);
    if ((tid & 31) == 0) red[tid >> 5] = s;
    __syncthreads();
    if (tid < 32) {
        float v = red[tid];
        #pragma unroll
        for (int o = 16; o; o >>= 1) v += __shfl_xor_sync(0xffffffffu, v, o);
        if (tid == 0) bval = v;
    }
    __syncthreads();
    float S = bval;
    #pragma unroll
    for (int i = 0; i < 4; i++) g_att[tid * 4 + i] = e[i] / S;
}

// ---------------- path_emb[j] = sum_p att[p]*h[p][j] ----------------
__global__ void pathemb_kernel() {
    __shared__ float s[256];
    int tid = threadIdx.x;
    int col = blockIdx.x * 32 + (tid & 31);
    int pg = tid >> 5;                         // 8 p-groups
    const float* h = g_hbuf[1];
    float acc = 0.0f;
    for (int p = pg * 512; p < pg * 512 + 512; p++) acc += g_att[p] * h[p * HID + col];
    s[tid] = acc;
    __syncthreads();
    if (pg == 0) {
        float v = s[tid];
        #pragma unroll
        for (int k = 1; k < 8; k++) v += s[k * 32 + tid];
        g_pe[col] = v;
    }
}

// ---------------- final linear + sigmoid ----------------
__global__ void final_kernel(const float* __restrict__ emb, const float* __restrict__ w_lin,
                             const float* __restrict__ b_lin, const int* __restrict__ user_id,
                             const int* __restrict__ item_id, float* __restrict__ out) {
    __shared__ float red[8];
    int tid = threadIdx.x;   // 256
    int u = user_id[0], it = item_id[0];
    float a = w_lin[tid] * emb[(size_t)u * DIM + tid]
            + w_lin[256 + tid] * emb[(size_t)it * DIM + tid]
            + w_lin[512 + tid] * g_pe[tid];
    #pragma unroll
    for (int o = 16; o; o >>= 1) a += __shfl_xor_sync(0xffffffffu, a, o);
    if ((tid & 31) == 0) red[tid >> 5] = a;
    __syncthreads();
    if (tid == 0) {
        float s = 0.0f;
        #pragma unroll
        for (int k = 0; k < 8; k++) s += red[k];
        out[0] = 1.0f / (1.0f + expf(-(s + b_lin[0])));
    }
}

// ---------------- host ----------------
extern "C" void kernel_launch(void* const* d_in, const int* in_sizes, int n_in,
                              void* d_out, int out_size) {
    const float* emb   = (const float*)d_in[0];
    const float* w_ih  = (const float*)d_in[1];
    const float* w_hh  = (const float*)d_in[2];
    const float* b_ih  = (const float*)d_in[3];
    const float* b_hh  = (const float*)d_in[4];
    const float* w_lin = (const float*)d_in[5];
    const float* b_lin = (const float*)d_in[6];
    const int* paths   = (const int*)d_in[7];
    const int* uid     = (const int*)d_in[8];
    const int* iid     = (const int*)d_in[9];
    float* out = (float*)d_out;

    cudaFuncSetAttribute(gemm_kernel<0>, cudaFuncAttributeMaxDynamicSharedMemorySize, SMEM_BYTES);
    cudaFuncSetAttribute(gemm_kernel<1>, cudaFuncAttributeMaxDynamicSharedMemorySize, SMEM_BYTES);

    prep_kernel<<<(NG * KDIM) / 256, 256>>>(w_ih, w_hh, b_ih, b_hh);

    // input projection for all 8 timesteps: M = 32768
    gemm_kernel<0><<<dim3(NG / BN, (LEN * PATHS) / BM), 256, SMEM_BYTES>>>(emb, paths, 0);

    // step 0 (h=c=0): pure cell update
    step0_kernel<<<(PATHS * HID) / 256, 256>>>();

    // steps 1..7: recurrent GEMM + fused cell
    for (int t = 1; t < LEN; t++)
        gemm_kernel<1><<<dim3(NG / BN, PATHS / BM), 256, SMEM_BYTES>>>(emb, paths, t);

    att_kernel<<<PATHS / 8, 256>>>();
    softmax_kernel<<<1, 1024>>>();
    pathemb_kernel<<<HID / 32, 256>>>();
    final_kernel<<<1, 256>>>(emb, w_lin, b_lin, uid, iid, out);
}

// round 3
// speedup vs baseline: 1.5209x; 1.5209x over previous
#include <cuda_runtime.h>
#include <cuda_bf16.h>
#include <cstdint>
#include <math.h>

#define PATHS 4096
#define LEN 8
#define DIM 256
#define HID 256
#define NG 1024   // 4*HID
#define KDIM 256

#define BM 128
#define BN 128
#define BK 32            // halves per k-chunk (64B per row)
#define ROWSTR 40        // halves per smem row (80B): 20 banks -> conflict-free ldmatrix
#define STAGEH ((BM + BN) * ROWSTR)          // halves per pipeline stage (10240)
#define NSTAGE 4
#define SMEM_BYTES (NSTAGE * STAGEH * 2)     // 81920 bytes

// ---------------- device scratch ----------------
__device__ __nv_bfloat16 g_GinH[(size_t)LEN * PATHS * NG];  // 64 MB precomputed input gates
__device__ __nv_bfloat16 g_x[(size_t)LEN * PATHS * DIM];    // 16 MB gathered+converted embeddings
__device__ __nv_bfloat16 g_WihH[NG * KDIM];                 // permuted bf16 w_ih (row 4j+q)
__device__ __nv_bfloat16 g_WhhH[NG * KDIM];                 // permuted bf16 w_hh
__device__ float g_bias[NG];
__device__ __nv_bfloat16 g_hbufH[2][PATHS * HID];
__device__ float g_cbuf[PATHS * HID];
__device__ float g_att[PATHS];
__device__ float g_pe[HID];

// ---------------- helpers ----------------
__device__ __forceinline__ void cp16(uint32_t smem_dst, const void* gmem_src) {
    asm volatile("cp.async.cg.shared.global [%0], [%1], 16;\n" :: "r"(smem_dst), "l"(gmem_src));
}
__device__ __forceinline__ void cp_commit() { asm volatile("cp.async.commit_group;\n"); }
template <int N>
__device__ __forceinline__ void cp_wait() { asm volatile("cp.async.wait_group %0;\n" :: "n"(N)); }

__device__ __forceinline__ void ldsm4(uint32_t* r, uint32_t saddr) {
    asm volatile("ldmatrix.sync.aligned.m8n8.x4.shared.b16 {%0,%1,%2,%3}, [%4];\n"
                 : "=r"(r[0]), "=r"(r[1]), "=r"(r[2]), "=r"(r[3]) : "r"(saddr));
}
__device__ __forceinline__ void mma_bf16(float* c, const uint32_t* a, const uint32_t* b) {
    asm volatile(
        "mma.sync.aligned.m16n8k16.row.col.f32.bf16.bf16.f32 "
        "{%0,%1,%2,%3},{%4,%5,%6,%7},{%8,%9},{%0,%1,%2,%3};\n"
        : "+f"(c[0]), "+f"(c[1]), "+f"(c[2]), "+f"(c[3])
        : "r"(a[0]), "r"(a[1]), "r"(a[2]), "r"(a[3]), "r"(b[0]), "r"(b[1]));
}
__device__ __forceinline__ float sigf(float x) { return 1.0f / (1.0f + __expf(-x)); }

// ---------------- weight permutation + bf16 convert: row 4j+q <- row q*HID+j ----------------
__global__ void prep_kernel(const float* __restrict__ w_ih, const float* __restrict__ w_hh,
                            const float* __restrict__ b_ih, const float* __restrict__ b_hh) {
    int idx = blockIdx.x * blockDim.x + threadIdx.x;
    if (idx < NG * KDIM) {
        int r = idx >> 8;
        int k = idx & 255;
        int j = r >> 2, q = r & 3;
        int src = (q * HID + j) * KDIM + k;
        g_WihH[idx] = __float2bfloat16(w_ih[src]);
        g_WhhH[idx] = __float2bfloat16(w_hh[src]);
        if (k == 0) g_bias[r] = b_ih[q * HID + j] + b_hh[q * HID + j];
    }
}

// ---------------- embedding gather + bf16 convert: g_x[m] = emb[paths[p*LEN+t]], m=t*4096+p ----
__global__ void gather_kernel(const float* __restrict__ emb, const int* __restrict__ paths) {
    int idx = blockIdx.x * blockDim.x + threadIdx.x;  // over 32768*64 float4 units
    int m = idx >> 6;
    int ch = idx & 63;
    int p = m & 4095, t = m >> 12;
    int node = paths[p * LEN + t];
    float4 v = *(const float4*)(emb + (size_t)node * DIM + ch * 4);
    __nv_bfloat162* dst = (__nv_bfloat162*)(g_x + (size_t)m * DIM + ch * 4);
    dst[0] = __floats2bfloat162_rn(v.x, v.y);
    dst[1] = __floats2bfloat162_rn(v.z, v.w);
}

// ---------------- unified bf16 GEMM ----------------
// MODE 0: GinH[m][n] = g_x[m] @ WihH^T + bias
// MODE 1: gates = GinH[t] + h_in @ WhhH^T ; fused LSTM cell epilogue
template <int MODE>
__global__ void __launch_bounds__(256, 2)
gemm_kernel(int t) {
    extern __shared__ __nv_bfloat16 smem[];
    const uint32_t smem_u32 = (uint32_t)__cvta_generic_to_shared(smem);
    const int tid = threadIdx.x;
    const int m0 = blockIdx.y * BM;
    const int n0 = blockIdx.x * BN;

    // ---- global source pointers for the copy plan: 1 thread per row, 4x cp16 ----
    const __nv_bfloat16* gsrc;
    if (tid < 128) {
        gsrc = (MODE == 0) ? (g_x + (size_t)(m0 + tid) * KDIM)
                           : (g_hbufH[(t + 1) & 1] + (size_t)(m0 + tid) * KDIM);
    } else {
        const __nv_bfloat16* B = (MODE == 0) ? g_WihH : g_WhhH;
        gsrc = B + (size_t)(n0 + tid - 128) * KDIM;
    }
    const uint32_t srow = smem_u32 + tid * (ROWSTR * 2);  // byte offset of this thread's row

    const int warp = tid >> 5, lane = tid & 31;
    const int wm = warp >> 1, wn = warp & 1;   // 4x2 warp grid, warp tile 32x64
    const int g = lane >> 2, t4 = lane & 3;

    // ldmatrix lane addressing (byte offsets within a stage)
    const int li = lane & 7;
    const int a_row_off = ((lane >> 3) & 1) * 8 + li;     // + rb
    const int a_k_off = (lane >> 4) * 8;                  // + kb
    const int b_row_off = ((lane >> 4) & 1) * 8 + li;     // + cb
    const int b_k_off = ((lane >> 3) & 1) * 8;            // + kb

    float acc[2][8][4];
    #pragma unroll
    for (int a = 0; a < 2; a++)
        #pragma unroll
        for (int b = 0; b < 8; b++)
            #pragma unroll
            for (int c = 0; c < 4; c++) acc[a][b][c] = 0.0f;

    // ---- prologue: issue stages 0..NSTAGE-2 ----
    #pragma unroll
    for (int s = 0; s < NSTAGE - 1; s++) {
        uint32_t dst = srow + s * (STAGEH * 2);
        const __nv_bfloat16* src = gsrc + s * BK;
        #pragma unroll
        for (int i = 0; i < 4; i++) cp16(dst + i * 16, src + i * 8);
        cp_commit();
    }

    #pragma unroll
    for (int kc = 0; kc < KDIM / BK; kc++) {
        if (kc < KDIM / BK - 2)      cp_wait<NSTAGE - 2>();
        else if (kc == KDIM / BK - 2) cp_wait<1>();
        else                          cp_wait<0>();
        __syncthreads();

        if (kc + NSTAGE - 1 < KDIM / BK) {
            int s = kc + NSTAGE - 1;
            uint32_t dst = srow + (s & (NSTAGE - 1)) * (STAGEH * 2);
            const __nv_bfloat16* src = gsrc + s * BK;
            #pragma unroll
            for (int i = 0; i < 4; i++) cp16(dst + i * 16, src + i * 8);
            cp_commit();
        }

        const uint32_t Abase = smem_u32 + (kc & (NSTAGE - 1)) * (STAGEH * 2);
        const uint32_t Bbase = Abase + BM * (ROWSTR * 2);

        #pragma unroll
        for (int s = 0; s < 2; s++) {           // two k16 steps per BK=32
            const int kb = s * 16;
            uint32_t afr[2][4], bfr[4][4];
            #pragma unroll
            for (int mt = 0; mt < 2; mt++) {
                int rb = wm * 32 + mt * 16;
                ldsm4(afr[mt], Abase + (rb + a_row_off) * (ROWSTR * 2) + (kb + a_k_off) * 2);
            }
            #pragma unroll
            for (int u = 0; u < 4; u++) {
                int cb = wn * 64 + u * 16;
                ldsm4(bfr[u], Bbase + (cb + b_row_off) * (ROWSTR * 2) + (kb + b_k_off) * 2);
            }
            #pragma unroll
            for (int mt = 0; mt < 2; mt++)
                #pragma unroll
                for (int u = 0; u < 4; u++) {
                    mma_bf16(acc[mt][2 * u],     afr[mt], &bfr[u][0]);
                    mma_bf16(acc[mt][2 * u + 1], afr[mt], &bfr[u][2]);
                }
        }
    }

    if (MODE == 0) {
        // epilogue: add bias, write GinH (bf16)
        #pragma unroll
        for (int mt = 0; mt < 2; mt++) {
            #pragma unroll
            for (int nt = 0; nt < 8; nt++) {
                int row = m0 + wm * 32 + mt * 16 + g;
                int col = n0 + wn * 64 + nt * 8 + 2 * t4;
                float b0 = g_bias[col], b1 = g_bias[col + 1];
                *(__nv_bfloat162*)&g_GinH[(size_t)row * NG + col] =
                    __floats2bfloat162_rn(acc[mt][nt][0] + b0, acc[mt][nt][1] + b1);
                *(__nv_bfloat162*)&g_GinH[(size_t)(row + 8) * NG + col] =
                    __floats2bfloat162_rn(acc[mt][nt][2] + b0, acc[mt][nt][3] + b1);
            }
        }
    } else {
        // fused LSTM cell epilogue: stage 64-row halves of the gate tile in smem (fp32)
        const size_t ginbase = (size_t)(t * PATHS + m0) * NG;
        __nv_bfloat16* hout = g_hbufH[t & 1];
        float* sg = (float*)smem;   // 64*128 fp32 = 32KB, reuses pipeline smem
        #pragma unroll
        for (int half = 0; half < 2; half++) {
            __syncthreads();
            if ((wm >> 1) == half) {
                #pragma unroll
                for (int mt = 0; mt < 2; mt++) {
                    #pragma unroll
                    for (int nt = 0; nt < 8; nt++) {
                        int lr = (wm & 1) * 32 + mt * 16 + g;
                        int col = wn * 64 + nt * 8 + 2 * t4;
                        int grow = half * 64 + lr;
                        const __nv_bfloat16* gin = &g_GinH[ginbase + (size_t)grow * NG + (n0 + col)];
                        __nv_bfloat162 g0 = *(const __nv_bfloat162*)(gin);
                        __nv_bfloat162 g1 = *(const __nv_bfloat162*)(gin + 8 * NG);
                        sg[lr * 128 + col]           = acc[mt][nt][0] + __bfloat162float(g0.x);
                        sg[lr * 128 + col + 1]       = acc[mt][nt][1] + __bfloat162float(g0.y);
                        sg[(lr + 8) * 128 + col]     = acc[mt][nt][2] + __bfloat162float(g1.x);
                        sg[(lr + 8) * 128 + col + 1] = acc[mt][nt][3] + __bfloat162float(g1.y);
                    }
                }
            }
            __syncthreads();
            #pragma unroll
            for (int i = 0; i < 8; i++) {
                int idx = tid + i * 256;
                int lr = idx >> 5, j = idx & 31;
                float4 gv = *(const float4*)(sg + lr * 128 + j * 4);
                int grow = m0 + half * 64 + lr;
                int jg = (n0 >> 2) + j;
                float ig = sigf(gv.x);
                float fg = sigf(gv.y);
                float gg = tanhf(gv.z);
                float og = sigf(gv.w);
                int ci = grow * HID + jg;
                float c = g_cbuf[ci];
                c = fg * c + ig * gg;
                g_cbuf[ci] = c;
                hout[ci] = __float2bfloat16(og * tanhf(c));
            }
        }
    }
}

// ---------------- step 0: h=c=0 -> cell update straight from GinH[0] ----------------
__global__ void step0_kernel() {
    int idx = blockIdx.x * blockDim.x + threadIdx.x;   // PATHS*HID
    const __nv_bfloat162* gp = (const __nv_bfloat162*)(g_GinH) + idx * 2;
    __nv_bfloat162 g0 = gp[0], g1 = gp[1];
    float ig = sigf(__bfloat162float(g0.x));
    float gg = tanhf(__bfloat162float(g1.x));
    float og = sigf(__bfloat162float(g1.y));
    float c = ig * gg;
    g_cbuf[idx] = c;
    g_hbufH[0][idx] = __float2bfloat16(og * tanhf(c));
}

// ---------------- attention logit: max over hidden ----------------
__global__ void att_kernel() {
    int warp = threadIdx.x >> 5, lane = threadIdx.x & 31;
    int p = blockIdx.x * 8 + warp;
    const __nv_bfloat16* h = g_hbufH[1] + p * HID;
    float m = -1e30f;
    #pragma unroll
    for (int k = lane; k < HID; k += 32) m = fmaxf(m, __bfloat162float(h[k]));
    #pragma unroll
    for (int o = 16; o; o >>= 1) m = fmaxf(m, __shfl_xor_sync(0xffffffffu, m, o));
    if (lane == 0) g_att[p] = m;
}

// ---------------- softmax over 4096 paths (single block) ----------------
__global__ void softmax_kernel() {
    __shared__ float red[32];
    __shared__ float bval;
    int tid = threadIdx.x;        // 1024 threads
    float l[4];
    float m = -1e30f;
    #pragma unroll
    for (int i = 0; i < 4; i++) { l[i] = g_att[tid * 4 + i]; m = fmaxf(m, l[i]); }
    #pragma unroll
    for (int o = 16; o; o >>= 1) m = fmaxf(m, __shfl_xor_sync(0xffffffffu, m, o));
    if ((tid & 31) == 0) red[tid >> 5] = m;
    __syncthreads();
    if (tid < 32) {
        float v = red[tid];
        #pragma unroll
        for (int o = 16; o; o >>= 1) v = fmaxf(v, __shfl_xor_sync(0xffffffffu, v, o));
        if (tid == 0) bval = v;
    }
    __syncthreads();
    float M = bval;
    float e[4], s = 0.0f;
    #pragma unroll
    for (int i = 0; i < 4; i++) { e[i] = expf(l[i] - M); s += e[i]; }
    #pragma unroll
    for (int o = 16; o; o >>= 1) s += __shfl_xor_sync(0xffffffffu, s, o);
    if ((tid & 31) == 0) red[tid >> 5] = s;
    __syncthreads();
    if (tid < 32) {
        float v = red[tid];
        #pragma unroll
        for (int o = 16; o; o >>= 1) v += __shfl_xor_sync(0xffffffffu, v, o);
        if (tid == 0) bval = v;
    }
    __syncthreads();
    float S = bval;
    #pragma unroll
    for (int i = 0; i < 4; i++) g_att[tid * 4 + i] = e[i] / S;
}

// ---------------- path_emb[j] = sum_p att[p]*h[p][j] ----------------
__global__ void pathemb_kernel() {
    __shared__ float s[256];
    int tid = threadIdx.x;
    int col = blockIdx.x * 32 + (tid & 31);
    int pg = tid >> 5;
    const __nv_bfloat16* h = g_hbufH[1];
    float acc = 0.0f;
    for (int p = pg * 512; p < pg * 512 + 512; p++)
        acc += g_att[p] * __bfloat162float(h[p * HID + col]);
    s[tid] = acc;
    __syncthreads();
    if (pg == 0) {
        float v = s[tid];
        #pragma unroll
        for (int k = 1; k < 8; k++) v += s[k * 32 + tid];
        g_pe[col] = v;
    }
}

// ---------------- final linear + sigmoid ----------------
__global__ void final_kernel(const float* __restrict__ emb, const float* __restrict__ w_lin,
                             const float* __restrict__ b_lin, const int* __restrict__ user_id,
                             const int* __restrict__ item_id, float* __restrict__ out) {
    __shared__ float red[8];
    int tid = threadIdx.x;   // 256
    int u = user_id[0], it = item_id[0];
    float a = w_lin[tid] * emb[(size_t)u * DIM + tid]
            + w_lin[256 + tid] * emb[(size_t)it * DIM + tid]
            + w_lin[512 + tid] * g_pe[tid];
    #pragma unroll
    for (int o = 16; o; o >>= 1) a += __shfl_xor_sync(0xffffffffu, a, o);
    if ((tid & 31) == 0) red[tid >> 5] = a;
    __syncthreads();
    if (tid == 0) {
        float s = 0.0f;
        #pragma unroll
        for (int k = 0; k < 8; k++) s += red[k];
        out[0] = 1.0f / (1.0f + expf(-(s + b_lin[0])));
    }
}

// ---------------- host ----------------
extern "C" void kernel_launch(void* const* d_in, const int* in_sizes, int n_in,
                              void* d_out, int out_size) {
    const float* emb   = (const float*)d_in[0];
    const float* w_ih  = (const float*)d_in[1];
    const float* w_hh  = (const float*)d_in[2];
    const float* b_ih  = (const float*)d_in[3];
    const float* b_hh  = (const float*)d_in[4];
    const float* w_lin = (const float*)d_in[5];
    const float* b_lin = (const float*)d_in[6];
    const int* paths   = (const int*)d_in[7];
    const int* uid     = (const int*)d_in[8];
    const int* iid     = (const int*)d_in[9];
    float* out = (float*)d_out;

    cudaFuncSetAttribute(gemm_kernel<0>, cudaFuncAttributeMaxDynamicSharedMemorySize, SMEM_BYTES);
    cudaFuncSetAttribute(gemm_kernel<1>, cudaFuncAttributeMaxDynamicSharedMemorySize, SMEM_BYTES);

    prep_kernel<<<(NG * KDIM) / 256, 256>>>(w_ih, w_hh, b_ih, b_hh);
    gather_kernel<<<(LEN * PATHS * 64) / 256, 256>>>(emb, paths);

    // input projection for all 8 timesteps: M = 32768
    gemm_kernel<0><<<dim3(NG / BN, (LEN * PATHS) / BM), 256, SMEM_BYTES>>>(0);

    // step 0 (h=c=0): pure cell update
    step0_kernel<<<(PATHS * HID) / 256, 256>>>();

    // steps 1..7: recurrent GEMM + fused cell
    for (int t = 1; t < LEN; t++)
        gemm_kernel<1><<<dim3(NG / BN, PATHS / BM), 256, SMEM_BYTES>>>(t);

    att_kernel<<<PATHS / 8, 256>>>();
    softmax_kernel<<<1, 1024>>>();
    pathemb_kernel<<<HID / 32, 256>>>();
    final_kernel<<<1, 256>>>(emb, w_lin, b_lin, uid, iid, out);
}

// round 6
// speedup vs baseline: 1.7526x; 1.1524x over previous
#include <cuda_runtime.h>
#include <cuda_bf16.h>
#include <cstdint>
#include <math.h>

#define PATHS 4096
#define LEN 8
#define DIM 256
#define HID 256
#define NG 1024   // 4*HID
#define KDIM 256

#define BM 128
#define BN 128
#define BK 32            // halves per k-chunk
#define ROWSTR 40        // halves per A/B pipeline smem row (80B)
#define STAGEH ((BM + BN) * ROWSTR)          // halves per stage for gemm0 (10240)
#define NSTAGE 4
#define SMEM_G0 (NSTAGE * STAGEH * 2)        // 81920 bytes

// persistent recurrence smem: A pipeline (4 x 128 x 40 halves) + persistent B (128 x 264 halves)
#define RSTR_B 264                           // halves per B row (528B)
#define SM_RA 0
#define SM_RA_STAGE (BM * ROWSTR * 2)        // 10240 B
#define SM_RB (NSTAGE * SM_RA_STAGE)         // 40960
#define SMEM_REC (SM_RB + BM * RSTR_B * 2)   // 40960 + 67584 = 108544

// ---------------- device scratch ----------------
__device__ __nv_bfloat16 g_GinH[(size_t)LEN * PATHS * NG];  // 64 MB precomputed input gates
__device__ __nv_bfloat16 g_x[(size_t)LEN * PATHS * DIM];    // 16 MB gathered+converted embeddings
__device__ __nv_bfloat16 g_WihH[NG * KDIM];                 // permuted bf16 w_ih (row 4j+q)
__device__ __nv_bfloat16 g_WhhH[NG * KDIM];                 // permuted bf16 w_hh
__device__ float g_bias[NG];
__device__ __nv_bfloat16 g_hbufH[2][PATHS * HID];
__device__ float g_cbuf[PATHS * HID];
__device__ unsigned g_att_u[PATHS];                         // monotonic-encoded float max
__device__ float g_att[PATHS];
__device__ float g_pe[HID];
__device__ unsigned g_cnt;                                  // persistent barrier arrivals
__device__ volatile unsigned g_gen;                         // persistent barrier generation

// ---------------- helpers ----------------
__device__ __forceinline__ void cp16(uint32_t smem_dst, const void* gmem_src) {
    asm volatile("cp.async.cg.shared.global [%0], [%1], 16;\n" :: "r"(smem_dst), "l"(gmem_src));
}
__device__ __forceinline__ void cp_commit() { asm volatile("cp.async.commit_group;\n"); }
template <int N>
__device__ __forceinline__ void cp_wait() { asm volatile("cp.async.wait_group %0;\n" :: "n"(N)); }

__device__ __forceinline__ void ldsm4(uint32_t* r, uint32_t saddr) {
    asm volatile("ldmatrix.sync.aligned.m8n8.x4.shared.b16 {%0,%1,%2,%3}, [%4];\n"
                 : "=r"(r[0]), "=r"(r[1]), "=r"(r[2]), "=r"(r[3]) : "r"(saddr));
}
__device__ __forceinline__ void mma_bf16(float* c, const uint32_t* a, const uint32_t* b) {
    asm volatile(
        "mma.sync.aligned.m16n8k16.row.col.f32.bf16.bf16.f32 "
        "{%0,%1,%2,%3},{%4,%5,%6,%7},{%8,%9},{%0,%1,%2,%3};\n"
        : "+f"(c[0]), "+f"(c[1]), "+f"(c[2]), "+f"(c[3])
        : "r"(a[0]), "r"(a[1]), "r"(a[2]), "r"(a[3]), "r"(b[0]), "r"(b[1]));
}
__device__ __forceinline__ float sigf(float x) { return 1.0f / (1.0f + __expf(-x)); }

__device__ __forceinline__ unsigned enc_f(float f) {
    unsigned b = __float_as_uint(f);
    return (b & 0x80000000u) ? ~b : (b | 0x80000000u);
}
__device__ __forceinline__ float dec_f(unsigned u) {
    unsigned b = (u & 0x80000000u) ? (u ^ 0x80000000u) : ~u;
    return __uint_as_float(b);
}

// ---------------- prep: weight permute + bf16, bias, barrier/att reset ----------------
__global__ void prep_kernel(const float* __restrict__ w_ih, const float* __restrict__ w_hh,
                            const float* __restrict__ b_ih, const float* __restrict__ b_hh) {
    int idx = blockIdx.x * blockDim.x + threadIdx.x;
    if (idx < NG * KDIM) {
        int r = idx >> 8;
        int k = idx & 255;
        int j = r >> 2, q = r & 3;
        int src = (q * HID + j) * KDIM + k;
        g_WihH[idx] = __float2bfloat16(w_ih[src]);
        g_WhhH[idx] = __float2bfloat16(w_hh[src]);
        if (k == 0) g_bias[r] = b_ih[q * HID + j] + b_hh[q * HID + j];
    }
    if (idx < PATHS) g_att_u[idx] = 0u;
    if (idx == 0) { g_cnt = 0u; g_gen = 0u; }
}

// ---------------- embedding gather + bf16 convert ----------------
__global__ void gather_kernel(const float* __restrict__ emb, const int* __restrict__ paths) {
    int idx = blockIdx.x * blockDim.x + threadIdx.x;  // over 32768*64 float4 units
    int m = idx >> 6;
    int ch = idx & 63;
    int p = m & 4095, t = m >> 12;
    int node = paths[p * LEN + t];
    float4 v = *(const float4*)(emb + (size_t)node * DIM + ch * 4);
    __nv_bfloat162* dst = (__nv_bfloat162*)(g_x + (size_t)m * DIM + ch * 4);
    dst[0] = __floats2bfloat162_rn(v.x, v.y);
    dst[1] = __floats2bfloat162_rn(v.z, v.w);
}

// ---------------- input projection GEMM (all 8 timesteps), fused step0 for t==0 rows ------
__global__ void __launch_bounds__(256, 2)
gemm0_kernel() {
    extern __shared__ __nv_bfloat16 smem[];
    const uint32_t smem_u32 = (uint32_t)__cvta_generic_to_shared(smem);
    const int tid = threadIdx.x;
    const int m0 = blockIdx.y * BM;
    const int n0 = blockIdx.x * BN;

    const __nv_bfloat16* gsrc = (tid < 128) ? (g_x + (size_t)(m0 + tid) * KDIM)
                                            : (g_WihH + (size_t)(n0 + tid - 128) * KDIM);
    const uint32_t srow = smem_u32 + tid * (ROWSTR * 2);

    const int warp = tid >> 5, lane = tid & 31;
    const int wm = warp >> 1, wn = warp & 1;
    const int g = lane >> 2, t4 = lane & 3;

    const int li = lane & 7;
    const int a_row_off = ((lane >> 3) & 1) * 8 + li;
    const int a_k_off = (lane >> 4) * 8;
    const int b_row_off = ((lane >> 4) & 1) * 8 + li;
    const int b_k_off = ((lane >> 3) & 1) * 8;

    float acc[2][8][4];
    #pragma unroll
    for (int a = 0; a < 2; a++)
        #pragma unroll
        for (int b = 0; b < 8; b++)
            #pragma unroll
            for (int c = 0; c < 4; c++) acc[a][b][c] = 0.0f;

    #pragma unroll
    for (int s = 0; s < NSTAGE - 1; s++) {
        uint32_t dst = srow + s * (STAGEH * 2);
        const __nv_bfloat16* src = gsrc + s * BK;
        #pragma unroll
        for (int i = 0; i < 4; i++) cp16(dst + i * 16, src + i * 8);
        cp_commit();
    }

    #pragma unroll
    for (int kc = 0; kc < KDIM / BK; kc++) {
        if (kc < KDIM / BK - 2)      cp_wait<NSTAGE - 2>();
        else if (kc == KDIM / BK - 2) cp_wait<1>();
        else                          cp_wait<0>();
        __syncthreads();

        if (kc + NSTAGE - 1 < KDIM / BK) {
            int s = kc + NSTAGE - 1;
            uint32_t dst = srow + (s & (NSTAGE - 1)) * (STAGEH * 2);
            const __nv_bfloat16* src = gsrc + s * BK;
            #pragma unroll
            for (int i = 0; i < 4; i++) cp16(dst + i * 16, src + i * 8);
            cp_commit();
        }

        const uint32_t Abase = smem_u32 + (kc & (NSTAGE - 1)) * (STAGEH * 2);
        const uint32_t Bbase = Abase + BM * (ROWSTR * 2);

        #pragma unroll
        for (int s = 0; s < 2; s++) {
            const int kb = s * 16;
            uint32_t afr[2][4], bfr[4][4];
            #pragma unroll
            for (int mt = 0; mt < 2; mt++) {
                int rb = wm * 32 + mt * 16;
                ldsm4(afr[mt], Abase + (rb + a_row_off) * (ROWSTR * 2) + (kb + a_k_off) * 2);
            }
            #pragma unroll
            for (int u = 0; u < 4; u++) {
                int cb = wn * 64 + u * 16;
                ldsm4(bfr[u], Bbase + (cb + b_row_off) * (ROWSTR * 2) + (kb + b_k_off) * 2);
            }
            #pragma unroll
            for (int mt = 0; mt < 2; mt++)
                #pragma unroll
                for (int u = 0; u < 4; u++) {
                    mma_bf16(acc[mt][2 * u],     afr[mt], &bfr[u][0]);
                    mma_bf16(acc[mt][2 * u + 1], afr[mt], &bfr[u][2]);
                }
        }
    }

    if (m0 < PATHS) {
        // t == 0 rows: fused step0 cell update (c_old = h_old = 0), nothing written to Gin
        #pragma unroll
        for (int mt = 0; mt < 2; mt++) {
            #pragma unroll
            for (int nt = 0; nt < 8; nt++) {
                int row = m0 + wm * 32 + mt * 16 + g;
                int col = n0 + wn * 64 + nt * 8 + 2 * t4;
                float b0 = g_bias[col], b1 = g_bias[col + 1];
                float v0 = acc[mt][nt][0] + b0, v1 = acc[mt][nt][1] + b1;
                float v2 = acc[mt][nt][2] + b0, v3 = acc[mt][nt][3] + b1;
                float r0 = __shfl_xor_sync(0xffffffffu, v0, 1);
                float r1 = __shfl_xor_sync(0xffffffffu, v1, 1);
                float r2 = __shfl_xor_sync(0xffffffffu, v2, 1);
                float r3 = __shfl_xor_sync(0xffffffffu, v3, 1);
                float q0, q2, q3; int rr, j;
                if ((t4 & 1) == 0) {         // even lane: quad for `row`, cols col..col+3
                    q0 = v0; q2 = r0; q3 = r1; rr = row; j = col >> 2;
                } else {                      // odd lane: quad for `row+8`, cols col-2..col+1
                    q0 = r2; q2 = v2; q3 = v3; rr = row + 8; j = (col - 2) >> 2;
                }
                float ig = sigf(q0);
                float gg = tanhf(q2);
                float og = sigf(q3);
                float c = ig * gg;
                g_cbuf[rr * HID + j] = c;
                g_hbufH[0][rr * HID + j] = __float2bfloat16(og * tanhf(c));
            }
        }
    } else {
        // t > 0 rows: add bias, write GinH (bf16)
        #pragma unroll
        for (int mt = 0; mt < 2; mt++) {
            #pragma unroll
            for (int nt = 0; nt < 8; nt++) {
                int row = m0 + wm * 32 + mt * 16 + g;
                int col = n0 + wn * 64 + nt * 8 + 2 * t4;
                float b0 = g_bias[col], b1 = g_bias[col + 1];
                *(__nv_bfloat162*)&g_GinH[(size_t)row * NG + col] =
                    __floats2bfloat162_rn(acc[mt][nt][0] + b0, acc[mt][nt][1] + b1);
                *(__nv_bfloat162*)&g_GinH[(size_t)(row + 8) * NG + col] =
                    __floats2bfloat162_rn(acc[mt][nt][2] + b0, acc[mt][nt][3] + b1);
            }
        }
    }
}

// ---------------- persistent recurrence: steps 1..7 in one kernel ----------------
// 256 CTAs (32 m-tiles x 8 n-tiles), all resident at 2 CTA/SM. B tile persists in smem;
// c persists in registers; device-wide barrier between steps; att max fused at t==7.
__global__ void __launch_bounds__(256, 2)
rec_kernel() {
    extern __shared__ __nv_bfloat16 smem[];
    const uint32_t sb = (uint32_t)__cvta_generic_to_shared(smem);
    const int tid = threadIdx.x;
    const int m0 = (blockIdx.x >> 3) * BM;
    const int n0 = (blockIdx.x & 7) * BN;

    const int warp = tid >> 5, lane = tid & 31;
    const int wm = warp >> 1, wn = warp & 1;
    const int g = lane >> 2, t4 = lane & 3;
    const int li = lane & 7;
    const int a_row_off = ((lane >> 3) & 1) * 8 + li;
    const int a_k_off = (lane >> 4) * 8;
    const int b_row_off = ((lane >> 4) & 1) * 8 + li;
    const int b_k_off = ((lane >> 3) & 1) * 8;

    // ---- load persistent B tile (Whh rows n0..n0+127, FULL K: 128 rows x 32 chunks) ----
    #pragma unroll
    for (int kk = 0; kk < 16; kk++) {
        int idx = tid + kk * 256;          // 4096 chunks of 16B
        int row = idx >> 5, ch = idx & 31;
        cp16(sb + SM_RB + row * (RSTR_B * 2) + ch * 16,
             g_WhhH + (size_t)(n0 + row) * KDIM + ch * 8);
    }
    cp_commit();

    // ---- load initial c into registers (mapping matches epilogue ownership) ----
    float creg[16];
    const int jg = (n0 >> 2) + lane;       // hidden unit owned by this lane
    #pragma unroll
    for (int half = 0; half < 2; half++)
        #pragma unroll
        for (int i = 0; i < 8; i++) {
            int grow = m0 + half * 64 + (tid >> 5) + 8 * i;
            creg[half * 8 + i] = g_cbuf[grow * HID + jg];
        }

    cp_wait<0>();
    __syncthreads();

    for (int t = 1; t < LEN; t++) {
        const __nv_bfloat16* asrc = g_hbufH[(t + 1) & 1] + (size_t)m0 * KDIM;

        float acc[2][8][4];
        #pragma unroll
        for (int a = 0; a < 2; a++)
            #pragma unroll
            for (int b = 0; b < 8; b++)
                #pragma unroll
                for (int c = 0; c < 4; c++) acc[a][b][c] = 0.0f;

        // A pipeline prologue (rows: tid<128 -> row tid)
        #pragma unroll
        for (int s = 0; s < NSTAGE - 1; s++) {
            if (tid < 128) {
                uint32_t dst = sb + SM_RA + s * SM_RA_STAGE + tid * (ROWSTR * 2);
                const __nv_bfloat16* src = asrc + tid * KDIM + s * BK;
                #pragma unroll
                for (int i = 0; i < 4; i++) cp16(dst + i * 16, src + i * 8);
            }
            cp_commit();
        }

        #pragma unroll
        for (int kc = 0; kc < KDIM / BK; kc++) {
            if (kc < KDIM / BK - 2)      cp_wait<NSTAGE - 2>();
            else if (kc == KDIM / BK - 2) cp_wait<1>();
            else                          cp_wait<0>();
            __syncthreads();

            if (kc + NSTAGE - 1 < KDIM / BK) {
                int s = kc + NSTAGE - 1;
                if (tid < 128) {
                    uint32_t dst = sb + SM_RA + (s & (NSTAGE - 1)) * SM_RA_STAGE + tid * (ROWSTR * 2);
                    const __nv_bfloat16* src = asrc + tid * KDIM + s * BK;
                    #pragma unroll
                    for (int i = 0; i < 4; i++) cp16(dst + i * 16, src + i * 8);
                }
                cp_commit();
            }

            const uint32_t Abase = sb + SM_RA + (kc & (NSTAGE - 1)) * SM_RA_STAGE;
            const uint32_t Bbase = sb + SM_RB;

            #pragma unroll
            for (int s = 0; s < 2; s++) {
                const int kb = s * 16;
                const int kT = kc * BK;
                uint32_t afr[2][4], bfr[4][4];
                #pragma unroll
                for (int mt = 0; mt < 2; mt++) {
                    int rb = wm * 32 + mt * 16;
                    ldsm4(afr[mt], Abase + (rb + a_row_off) * (ROWSTR * 2) + (kb + a_k_off) * 2);
                }
                #pragma unroll
                for (int u = 0; u < 4; u++) {
                    int cb = wn * 64 + u * 16;
                    ldsm4(bfr[u], Bbase + (cb + b_row_off) * (RSTR_B * 2) + (kT + kb + b_k_off) * 2);
                }
                #pragma unroll
                for (int mt = 0; mt < 2; mt++)
                    #pragma unroll
                    for (int u = 0; u < 4; u++) {
                        mma_bf16(acc[mt][2 * u],     afr[mt], &bfr[u][0]);
                        mma_bf16(acc[mt][2 * u + 1], afr[mt], &bfr[u][2]);
                    }
            }
        }

        // ---- fused LSTM cell epilogue (stages gates in A-region smem) ----
        const size_t ginbase = (size_t)(t * PATHS + m0) * NG;
        __nv_bfloat16* hout = g_hbufH[t & 1];
        float* sg = (float*)smem;    // 64*128 fp32 = 32KB <= 40KB A region
        #pragma unroll
        for (int half = 0; half < 2; half++) {
            __syncthreads();
            if ((wm >> 1) == half) {
                #pragma unroll
                for (int mt = 0; mt < 2; mt++) {
                    #pragma unroll
                    for (int nt = 0; nt < 8; nt++) {
                        int lr = (wm & 1) * 32 + mt * 16 + g;
                        int col = wn * 64 + nt * 8 + 2 * t4;
                        int grow = half * 64 + lr;
                        const __nv_bfloat16* gin = &g_GinH[ginbase + (size_t)grow * NG + (n0 + col)];
                        __nv_bfloat162 g0 = *(const __nv_bfloat162*)(gin);
                        __nv_bfloat162 g1 = *(const __nv_bfloat162*)(gin + 8 * NG);
                        sg[lr * 128 + col]           = acc[mt][nt][0] + __bfloat162float(g0.x);
                        sg[lr * 128 + col + 1]       = acc[mt][nt][1] + __bfloat162float(g0.y);
                        sg[(lr + 8) * 128 + col]     = acc[mt][nt][2] + __bfloat162float(g1.x);
                        sg[(lr + 8) * 128 + col + 1] = acc[mt][nt][3] + __bfloat162float(g1.y);
                    }
                }
            }
            __syncthreads();
            #pragma unroll
            for (int i = 0; i < 8; i++) {
                int lr = (tid >> 5) + 8 * i;        // row within half; lane j fixed
                float4 gv = *(const float4*)(sg + lr * 128 + lane * 4);
                int grow = m0 + half * 64 + lr;
                float ig = sigf(gv.x);
                float fg = sigf(gv.y);
                float gg = tanhf(gv.z);
                float og = sigf(gv.w);
                float c = fg * creg[half * 8 + i] + ig * gg;
                creg[half * 8 + i] = c;
                float h = og * tanhf(c);
                hout[grow * HID + jg] = __float2bfloat16(h);
                if (t == LEN - 1) {
                    // warp-level max over this CTA's 32 hidden units for row `grow`
                    float m = h;
                    #pragma unroll
                    for (int o = 16; o; o >>= 1) m = fmaxf(m, __shfl_xor_sync(0xffffffffu, m, o));
                    if (lane == 0) atomicMax(&g_att_u[grow], enc_f(m));
                }
            }
        }

        // ---- device-wide barrier ----
        __threadfence();
        __syncthreads();
        if (tid == 0) {
            unsigned old = atomicAdd(&g_cnt, 1u);
            if (old == (unsigned)(t * 256 - 1)) {
                __threadfence();
                g_gen = (unsigned)t;
            }
            while (g_gen < (unsigned)t) { }
            __threadfence();
        }
        __syncthreads();
    }
}

// ---------------- softmax over 4096 paths (single block, decodes att encoding) ----------------
__global__ void softmax_kernel() {
    __shared__ float red[32];
    __shared__ float bval;
    int tid = threadIdx.x;        // 1024 threads
    float l[4];
    float m = -1e30f;
    #pragma unroll
    for (int i = 0; i < 4; i++) { l[i] = dec_f(g_att_u[tid * 4 + i]); m = fmaxf(m, l[i]); }
    #pragma unroll
    for (int o = 16; o; o >>= 1) m = fmaxf(m, __shfl_xor_sync(0xffffffffu, m, o));
    if ((tid & 31) == 0) red[tid >> 5] = m;
    __syncthreads();
    if (tid < 32) {
        float v = red[tid];
        #pragma unroll
        for (int o = 16; o; o >>= 1) v = fmaxf(v, __shfl_xor_sync(0xffffffffu, v, o));
        if (tid == 0) bval = v;
    }
    __syncthreads();
    float M = bval;
    float e[4], s = 0.0f;
    #pragma unroll
    for (int i = 0; i < 4; i++) { e[i] = expf(l[i] - M); s += e[i]; }
    #pragma unroll
    for (int o = 16; o; o >>= 1) s += __shfl_xor_sync(0xffffffffu, s, o);
    if ((tid & 31) == 0) red[tid >> 5] = s;
    __syncthreads();
    if (tid < 32) {
        float v = red[tid];
        #pragma unroll
        for (int o = 16; o; o >>= 1) v += __shfl_xor_sync(0xffffffffu, v, o);
        if (tid == 0) bval = v;
    }
    __syncthreads();
    float S = bval;
    #pragma unroll
    for (int i = 0; i < 4; i++) g_att[tid * 4 + i] = e[i] / S;
}

// ---------------- path_emb[j] = sum_p att[p]*h[p][j] ----------------
__global__ void pathemb_kernel() {
    __shared__ float s[256];
    int tid = threadIdx.x;
    int col = blockIdx.x * 32 + (tid & 31);
    int pg = tid >> 5;
    const __nv_bfloat16* h = g_hbufH[1];
    float acc = 0.0f;
    for (int p = pg * 512; p < pg * 512 + 512; p++)
        acc += g_att[p] * __bfloat162float(h[p * HID + col]);
    s[tid] = acc;
    __syncthreads();
    if (pg == 0) {
        float v = s[tid];
        #pragma unroll
        for (int k = 1; k < 8; k++) v += s[k * 32 + tid];
        g_pe[col] = v;
    }
}

// ---------------- final linear + sigmoid ----------------
__global__ void final_kernel(const float* __restrict__ emb, const float* __restrict__ w_lin,
                             const float* __restrict__ b_lin, const int* __restrict__ user_id,
                             const int* __restrict__ item_id, float* __restrict__ out) {
    __shared__ float red[8];
    int tid = threadIdx.x;   // 256
    int u = user_id[0], it = item_id[0];
    float a = w_lin[tid] * emb[(size_t)u * DIM + tid]
            + w_lin[256 + tid] * emb[(size_t)it * DIM + tid]
            + w_lin[512 + tid] * g_pe[tid];
    #pragma unroll
    for (int o = 16; o; o >>= 1) a += __shfl_xor_sync(0xffffffffu, a, o);
    if ((tid & 31) == 0) red[tid >> 5] = a;
    __syncthreads();
    if (tid == 0) {
        float s = 0.0f;
        #pragma unroll
        for (int k = 0; k < 8; k++) s += red[k];
        out[0] = 1.0f / (1.0f + expf(-(s + b_lin[0])));
    }
}

// ---------------- host ----------------
extern "C" void kernel_launch(void* const* d_in, const int* in_sizes, int n_in,
                              void* d_out, int out_size) {
    const float* emb   = (const float*)d_in[0];
    const float* w_ih  = (const float*)d_in[1];
    const float* w_hh  = (const float*)d_in[2];
    const float* b_ih  = (const float*)d_in[3];
    const float* b_hh  = (const float*)d_in[4];
    const float* w_lin = (const float*)d_in[5];
    const float* b_lin = (const float*)d_in[6];
    const int* paths   = (const int*)d_in[7];
    const int* uid     = (const int*)d_in[8];
    const int* iid     = (const int*)d_in[9];
    float* out = (float*)d_out;

    cudaFuncSetAttribute(gemm0_kernel, cudaFuncAttributeMaxDynamicSharedMemorySize, SMEM_G0);
    cudaFuncSetAttribute(rec_kernel, cudaFuncAttributeMaxDynamicSharedMemorySize, SMEM_REC);

    prep_kernel<<<(NG * KDIM) / 256, 256>>>(w_ih, w_hh, b_ih, b_hh);
    gather_kernel<<<(LEN * PATHS * 64) / 256, 256>>>(emb, paths);

    // input projection for all 8 timesteps (M=32768); t==0 tiles do the step0 cell update inline
    gemm0_kernel<<<dim3(NG / BN, (LEN * PATHS) / BM), 256, SMEM_G0>>>();

    // steps 1..7 in ONE persistent kernel (256 CTAs, device-wide barrier between steps)
    rec_kernel<<<256, 256, SMEM_REC>>>();

    softmax_kernel<<<1, 1024>>>();
    pathemb_kernel<<<HID / 32, 256>>>();
    final_kernel<<<1, 256>>>(emb, w_lin, b_lin, uid, iid, out);
}

// round 9
// speedup vs baseline: 1.9278x; 1.1000x over previous
#include <cuda_runtime.h>
#include <cuda_bf16.h>
#include <cstdint>
#include <math.h>

#define PATHS 4096
#define LEN 8
#define DIM 256
#define HID 256
#define NG 1024   // 4*HID
#define KDIM 256

#define BM 128
#define BN 128
#define BK 32            // halves per k-chunk
#define ROWSTR 40        // halves per A pipeline smem row (80B)
#define STAGEH ((BM + BN) * ROWSTR)          // halves per stage for gemm0
#define NSTAGE 4
#define SMEM_G0 (NSTAGE * STAGEH * 2)        // 81920 bytes

// ---- persistent recurrence v2: 128 CTAs x 512 threads, BM=256 x BN=128, 1 CTA/SM ----
#define R_BM 256
#define R_BN 128
#define RSTR_B 264                            // halves per B row (528B)
#define R_ASTG (R_BM * ROWSTR * 2)            // 20480 B per A stage
#define R_SMB (3 * R_ASTG)                    // 61440: B tile offset
#define R_SMG (R_SMB + R_BN * RSTR_B * 2)     // 129024: Gin tile offset
#define R_GSTR 136                            // halves per Gin smem row (272B -> conflict-free)
#define SMEM_REC2 (R_SMG + R_BM * R_GSTR * 2) // 198656
#define R_CTAS 128

// ---------------- device scratch ----------------
__device__ __nv_bfloat16 g_GinH[(size_t)LEN * PATHS * NG];  // 64 MB precomputed input gates
__device__ __nv_bfloat16 g_x[(size_t)LEN * PATHS * DIM];    // 16 MB gathered+converted embeddings
__device__ __nv_bfloat16 g_WihH[NG * KDIM];                 // permuted bf16 w_ih (row 4j+q)
__device__ __nv_bfloat16 g_WhhH[NG * KDIM];                 // permuted bf16 w_hh
__device__ float g_bias[NG];
__device__ __nv_bfloat16 g_hbufH[2][PATHS * HID];
__device__ float g_cbuf[PATHS * HID];
__device__ unsigned g_att_u[PATHS];                         // monotonic-encoded float max
__device__ float g_att[PATHS];
__device__ float g_pe[HID];
__device__ unsigned g_cnt;                                  // persistent barrier arrivals
__device__ volatile unsigned g_gen;                         // persistent barrier generation

// ---------------- helpers ----------------
__device__ __forceinline__ void cp16(uint32_t smem_dst, const void* gmem_src) {
    asm volatile("cp.async.cg.shared.global [%0], [%1], 16;\n" :: "r"(smem_dst), "l"(gmem_src));
}
__device__ __forceinline__ void cp_commit() { asm volatile("cp.async.commit_group;\n"); }
template <int N>
__device__ __forceinline__ void cp_wait() { asm volatile("cp.async.wait_group %0;\n" :: "n"(N)); }

__device__ __forceinline__ void ldsm4(uint32_t* r, uint32_t saddr) {
    asm volatile("ldmatrix.sync.aligned.m8n8.x4.shared.b16 {%0,%1,%2,%3}, [%4];\n"
                 : "=r"(r[0]), "=r"(r[1]), "=r"(r[2]), "=r"(r[3]) : "r"(saddr));
}
__device__ __forceinline__ void mma_bf16(float* c, const uint32_t* a, const uint32_t* b) {
    asm volatile(
        "mma.sync.aligned.m16n8k16.row.col.f32.bf16.bf16.f32 "
        "{%0,%1,%2,%3},{%4,%5,%6,%7},{%8,%9},{%0,%1,%2,%3};\n"
        : "+f"(c[0]), "+f"(c[1]), "+f"(c[2]), "+f"(c[3])
        : "r"(a[0]), "r"(a[1]), "r"(a[2]), "r"(a[3]), "r"(b[0]), "r"(b[1]));
}
__device__ __forceinline__ float sigf(float x) { return __fdividef(1.0f, 1.0f + __expf(-x)); }
__device__ __forceinline__ float tanh_fast(float x) {
    float e = __expf(2.0f * x);
    return 1.0f - __fdividef(2.0f, e + 1.0f);
}

__device__ __forceinline__ unsigned enc_f(float f) {
    unsigned b = __float_as_uint(f);
    return (b & 0x80000000u) ? ~b : (b | 0x80000000u);
}
__device__ __forceinline__ float dec_f(unsigned u) {
    unsigned b = (u & 0x80000000u) ? (u ^ 0x80000000u) : ~u;
    return __uint_as_float(b);
}

// ---------------- prep: weight permute + bf16, bias, barrier/att reset ----------------
__global__ void prep_kernel(const float* __restrict__ w_ih, const float* __restrict__ w_hh,
                            const float* __restrict__ b_ih, const float* __restrict__ b_hh) {
    int idx = blockIdx.x * blockDim.x + threadIdx.x;
    if (idx < NG * KDIM) {
        int r = idx >> 8;
        int k = idx & 255;
        int j = r >> 2, q = r & 3;
        int src = (q * HID + j) * KDIM + k;
        g_WihH[idx] = __float2bfloat16(w_ih[src]);
        g_WhhH[idx] = __float2bfloat16(w_hh[src]);
        if (k == 0) g_bias[r] = b_ih[q * HID + j] + b_hh[q * HID + j];
    }
    if (idx < PATHS) g_att_u[idx] = 0u;
    if (idx == 0) { g_cnt = 0u; g_gen = 0u; }
}

// ---------------- embedding gather + bf16 convert ----------------
__global__ void gather_kernel(const float* __restrict__ emb, const int* __restrict__ paths) {
    int idx = blockIdx.x * blockDim.x + threadIdx.x;  // over 32768*64 float4 units
    int m = idx >> 6;
    int ch = idx & 63;
    int p = m & 4095, t = m >> 12;
    int node = paths[p * LEN + t];
    float4 v = *(const float4*)(emb + (size_t)node * DIM + ch * 4);
    __nv_bfloat162* dst = (__nv_bfloat162*)(g_x + (size_t)m * DIM + ch * 4);
    dst[0] = __floats2bfloat162_rn(v.x, v.y);
    dst[1] = __floats2bfloat162_rn(v.z, v.w);
}

// ---------------- input projection GEMM (all 8 timesteps), fused step0 for t==0 rows ------
__global__ void __launch_bounds__(256, 2)
gemm0_kernel() {
    extern __shared__ __nv_bfloat16 smem[];
    const uint32_t smem_u32 = (uint32_t)__cvta_generic_to_shared(smem);
    const int tid = threadIdx.x;
    const int m0 = blockIdx.y * BM;
    const int n0 = blockIdx.x * BN;

    const __nv_bfloat16* gsrc = (tid < 128) ? (g_x + (size_t)(m0 + tid) * KDIM)
                                            : (g_WihH + (size_t)(n0 + tid - 128) * KDIM);
    const uint32_t srow = smem_u32 + tid * (ROWSTR * 2);

    const int warp = tid >> 5, lane = tid & 31;
    const int wm = warp >> 1, wn = warp & 1;
    const int g = lane >> 2, t4 = lane & 3;

    const int li = lane & 7;
    const int a_row_off = ((lane >> 3) & 1) * 8 + li;
    const int a_k_off = (lane >> 4) * 8;
    const int b_row_off = ((lane >> 4) & 1) * 8 + li;
    const int b_k_off = ((lane >> 3) & 1) * 8;

    float acc[2][8][4];
    #pragma unroll
    for (int a = 0; a < 2; a++)
        #pragma unroll
        for (int b = 0; b < 8; b++)
            #pragma unroll
            for (int c = 0; c < 4; c++) acc[a][b][c] = 0.0f;

    #pragma unroll
    for (int s = 0; s < NSTAGE - 1; s++) {
        uint32_t dst = srow + s * (STAGEH * 2);
        const __nv_bfloat16* src = gsrc + s * BK;
        #pragma unroll
        for (int i = 0; i < 4; i++) cp16(dst + i * 16, src + i * 8);
        cp_commit();
    }

    #pragma unroll
    for (int kc = 0; kc < KDIM / BK; kc++) {
        if (kc < KDIM / BK - 2)      cp_wait<NSTAGE - 2>();
        else if (kc == KDIM / BK - 2) cp_wait<1>();
        else                          cp_wait<0>();
        __syncthreads();

        if (kc + NSTAGE - 1 < KDIM / BK) {
            int s = kc + NSTAGE - 1;
            uint32_t dst = srow + (s & (NSTAGE - 1)) * (STAGEH * 2);
            const __nv_bfloat16* src = gsrc + s * BK;
            #pragma unroll
            for (int i = 0; i < 4; i++) cp16(dst + i * 16, src + i * 8);
            cp_commit();
        }

        const uint32_t Abase = smem_u32 + (kc & (NSTAGE - 1)) * (STAGEH * 2);
        const uint32_t Bbase = Abase + BM * (ROWSTR * 2);

        #pragma unroll
        for (int s = 0; s < 2; s++) {
            const int kb = s * 16;
            uint32_t afr[2][4], bfr[4][4];
            #pragma unroll
            for (int mt = 0; mt < 2; mt++) {
                int rb = wm * 32 + mt * 16;
                ldsm4(afr[mt], Abase + (rb + a_row_off) * (ROWSTR * 2) + (kb + a_k_off) * 2);
            }
            #pragma unroll
            for (int u = 0; u < 4; u++) {
                int cb = wn * 64 + u * 16;
                ldsm4(bfr[u], Bbase + (cb + b_row_off) * (ROWSTR * 2) + (kb + b_k_off) * 2);
            }
            #pragma unroll
            for (int mt = 0; mt < 2; mt++)
                #pragma unroll
                for (int u = 0; u < 4; u++) {
                    mma_bf16(acc[mt][2 * u],     afr[mt], &bfr[u][0]);
                    mma_bf16(acc[mt][2 * u + 1], afr[mt], &bfr[u][2]);
                }
        }
    }

    if (m0 < PATHS) {
        // t == 0 rows: fused step0 cell update (c_old = h_old = 0)
        #pragma unroll
        for (int mt = 0; mt < 2; mt++) {
            #pragma unroll
            for (int nt = 0; nt < 8; nt++) {
                int row = m0 + wm * 32 + mt * 16 + g;
                int col = n0 + wn * 64 + nt * 8 + 2 * t4;
                float b0 = g_bias[col], b1 = g_bias[col + 1];
                float v0 = acc[mt][nt][0] + b0, v1 = acc[mt][nt][1] + b1;
                float v2 = acc[mt][nt][2] + b0, v3 = acc[mt][nt][3] + b1;
                float r0 = __shfl_xor_sync(0xffffffffu, v0, 1);
                float r1 = __shfl_xor_sync(0xffffffffu, v1, 1);
                float r2 = __shfl_xor_sync(0xffffffffu, v2, 1);
                float r3 = __shfl_xor_sync(0xffffffffu, v3, 1); (void)r3;
                float q0, q2, q3; int rr, j;
                if ((t4 & 1) == 0) {
                    q0 = v0; q2 = r0; q3 = r1; rr = row; j = col >> 2;
                } else {
                    q0 = r2; q2 = v2; q3 = v3; rr = row + 8; j = (col - 2) >> 2;
                }
                float ig = sigf(q0);
                float gg = tanh_fast(q2);
                float og = sigf(q3);
                float c = ig * gg;
                g_cbuf[rr * HID + j] = c;
                g_hbufH[0][rr * HID + j] = __float2bfloat16(og * tanh_fast(c));
            }
        }
    } else {
        // t > 0 rows: add bias, write GinH (bf16)
        #pragma unroll
        for (int mt = 0; mt < 2; mt++) {
            #pragma unroll
            for (int nt = 0; nt < 8; nt++) {
                int row = m0 + wm * 32 + mt * 16 + g;
                int col = n0 + wn * 64 + nt * 8 + 2 * t4;
                float b0 = g_bias[col], b1 = g_bias[col + 1];
                *(__nv_bfloat162*)&g_GinH[(size_t)row * NG + col] =
                    __floats2bfloat162_rn(acc[mt][nt][0] + b0, acc[mt][nt][1] + b1);
                *(__nv_bfloat162*)&g_GinH[(size_t)(row + 8) * NG + col] =
                    __floats2bfloat162_rn(acc[mt][nt][2] + b0, acc[mt][nt][3] + b1);
            }
        }
    }
}

// ---------------- persistent recurrence v2: steps 1..7, 128 CTAs x 512 threads ----------------
// BM=256 x BN=128 per CTA, exactly 1 CTA/SM. Whh persists in smem; Gin prefetched to smem;
// c in registers; staging-free shfl-pair epilogue; device barrier between steps.
__global__ void __launch_bounds__(512, 1)
rec_kernel() {
    extern __shared__ __nv_bfloat16 smem[];
    const uint32_t sb = (uint32_t)__cvta_generic_to_shared(smem);
    const int tid = threadIdx.x;
    const int m0 = (blockIdx.x >> 3) * R_BM;
    const int n0 = (blockIdx.x & 7) * R_BN;

    const int warp = tid >> 5, lane = tid & 31;
    const int wm = warp >> 1, wn = warp & 1;     // 8 x 2 warps, warp tile 32 x 64
    const int g = lane >> 2, t4 = lane & 3;
    const int li = lane & 7;
    const int a_row_off = ((lane >> 3) & 1) * 8 + li;
    const int a_k_off = (lane >> 4) * 8;
    const int b_row_off = ((lane >> 4) & 1) * 8 + li;
    const int b_k_off = ((lane >> 3) & 1) * 8;

    // ---- persistent B tile: Whh rows n0..n0+127, full K (4096 x 16B chunks) ----
    #pragma unroll
    for (int kk = 0; kk < 8; kk++) {
        int idx = tid + kk * 512;
        int row = idx >> 5, ch = idx & 31;
        cp16(sb + R_SMB + row * (RSTR_B * 2) + ch * 16,
             g_WhhH + (size_t)(n0 + row) * KDIM + ch * 8);
    }
    // B commits together with first A stage of step 1 (group s0)

    // ---- initial c into registers; ownership fixed per thread ----
    float creg[16];
    const int odd = t4 & 1;
    const int rbase = wm * 32 + g + (odd ? 8 : 0);     // + mt*16
    const int jbase = (n0 >> 2) + wn * 16 + (t4 >> 1); // + 2*nt
    #pragma unroll
    for (int mt = 0; mt < 2; mt++)
        #pragma unroll
        for (int nt = 0; nt < 8; nt++)
            creg[mt * 8 + nt] = g_cbuf[(m0 + rbase + mt * 16) * HID + jbase + 2 * nt];

    for (int t = 1; t < LEN; t++) {
        const __nv_bfloat16* asrc = g_hbufH[(t + 1) & 1] + (size_t)m0 * KDIM;
        const int arow = tid >> 1;
        const int aoff = (tid & 1) * 16;   // halves

        float acc[2][8][4];
        #pragma unroll
        for (int a = 0; a < 2; a++)
            #pragma unroll
            for (int b = 0; b < 8; b++)
                #pragma unroll
                for (int c = 0; c < 4; c++) acc[a][b][c] = 0.0f;

        // prologue: s0 (group 0, includes B at t==1), s1 (group 1), Gin (group 2)
        #pragma unroll
        for (int s = 0; s < 2; s++) {
            uint32_t dst = sb + s * R_ASTG + arow * (ROWSTR * 2) + aoff * 2;
            const __nv_bfloat16* src = asrc + arow * KDIM + s * BK + aoff;
            cp16(dst, src); cp16(dst + 16, src + 8);
            cp_commit();
        }
        {
            // Gin tile: 256 rows x 128 cols bf16 = 4096 x 16B chunks
            const __nv_bfloat16* gsrc = g_GinH + ((size_t)t * PATHS + m0) * NG + n0;
            #pragma unroll
            for (int kk = 0; kk < 8; kk++) {
                int idx = tid + kk * 512;
                int row = idx >> 4, ch = idx & 15;
                cp16(sb + R_SMG + row * (R_GSTR * 2) + ch * 16, gsrc + (size_t)row * NG + ch * 8);
            }
            cp_commit();
        }

        #pragma unroll
        for (int kc = 0; kc < KDIM / BK; kc++) {
            if (kc <= 1)      cp_wait<2>();
            else if (kc <= 6) cp_wait<1>();
            else              cp_wait<0>();
            __syncthreads();

            if (kc + 2 < KDIM / BK) {
                int s = kc + 2;
                uint32_t dst = sb + (s % 3) * R_ASTG + arow * (ROWSTR * 2) + aoff * 2;
                const __nv_bfloat16* src = asrc + arow * KDIM + s * BK + aoff;
                cp16(dst, src); cp16(dst + 16, src + 8);
                cp_commit();
            }

            const uint32_t Abase = sb + (kc % 3) * R_ASTG;
            const uint32_t Bbase = sb + R_SMB;

            #pragma unroll
            for (int s = 0; s < 2; s++) {
                const int kb = s * 16;
                const int kT = kc * BK;
                uint32_t afr[2][4], bfr[4][4];
                #pragma unroll
                for (int mt = 0; mt < 2; mt++) {
                    int rb = wm * 32 + mt * 16;
                    ldsm4(afr[mt], Abase + (rb + a_row_off) * (ROWSTR * 2) + (kb + a_k_off) * 2);
                }
                #pragma unroll
                for (int u = 0; u < 4; u++) {
                    int cb = wn * 64 + u * 16;
                    ldsm4(bfr[u], Bbase + (cb + b_row_off) * (RSTR_B * 2) + (kT + kb + b_k_off) * 2);
                }
                #pragma unroll
                for (int mt = 0; mt < 2; mt++)
                    #pragma unroll
                    for (int u = 0; u < 4; u++) {
                        mma_bf16(acc[mt][2 * u],     afr[mt], &bfr[u][0]);
                        mma_bf16(acc[mt][2 * u + 1], afr[mt], &bfr[u][2]);
                    }
            }
        }

        // ---- staging-free fused LSTM cell epilogue ----
        __nv_bfloat16* hout = g_hbufH[t & 1];
        #pragma unroll
        for (int mt = 0; mt < 2; mt++) {
            float hmax = -1e30f;
            #pragma unroll
            for (int nt = 0; nt < 8; nt++) {
                int rowA = wm * 32 + mt * 16 + g;            // local row of v0/v1
                int cl = wn * 64 + nt * 8 + 2 * t4;          // local col of v0
                const char* gb = (const char*)smem + R_SMG;
                __nv_bfloat162 g0 = *(const __nv_bfloat162*)(gb + rowA * (R_GSTR * 2) + cl * 2);
                __nv_bfloat162 g1 = *(const __nv_bfloat162*)(gb + (rowA + 8) * (R_GSTR * 2) + cl * 2);
                float v0 = acc[mt][nt][0] + __bfloat162float(g0.x);
                float v1 = acc[mt][nt][1] + __bfloat162float(g0.y);
                float v2 = acc[mt][nt][2] + __bfloat162float(g1.x);
                float v3 = acc[mt][nt][3] + __bfloat162float(g1.y);
                float r0 = __shfl_xor_sync(0xffffffffu, v0, 1);
                float r1 = __shfl_xor_sync(0xffffffffu, v1, 1);
                float r2 = __shfl_xor_sync(0xffffffffu, v2, 1);
                float r3 = __shfl_xor_sync(0xffffffffu, v3, 1);
                float qi, qf, qg, qo;
                if (!odd) { qi = v0; qf = v1; qg = r0; qo = r1; }
                else      { qi = r2; qf = r3; qg = v2; qo = v3; }
                float ig = sigf(qi);
                float fg = sigf(qf);
                float gg = tanh_fast(qg);
                float og = sigf(qo);
                float c = fg * creg[mt * 8 + nt] + ig * gg;
                creg[mt * 8 + nt] = c;
                float h = og * tanh_fast(c);
                hout[(m0 + rbase + mt * 16) * HID + jbase + 2 * nt] = __float2bfloat16(h);
                hmax = fmaxf(hmax, h);
            }
            if (t == LEN - 1) {
                // combine t4 pairs {0,2} / {1,3} (same row, complementary j sets)
                hmax = fmaxf(hmax, __shfl_xor_sync(0xffffffffu, hmax, 2));
                if (t4 < 2) atomicMax(&g_att_u[m0 + rbase + mt * 16], enc_f(hmax));
            }
        }

        // ---- device-wide barrier ----
        __threadfence();
        __syncthreads();
        if (tid == 0) {
            unsigned old = atomicAdd(&g_cnt, 1u);
            if (old == (unsigned)(t * R_CTAS - 1)) {
                __threadfence();
                g_gen = (unsigned)t;
            }
            while (g_gen < (unsigned)t) { }
            __threadfence();
        }
        __syncthreads();
    }
}

// ---------------- softmax over 4096 paths (single block, decodes att encoding) ----------------
__global__ void softmax_kernel() {
    __shared__ float red[32];
    __shared__ float bval;
    int tid = threadIdx.x;        // 1024 threads
    float l[4];
    float m = -1e30f;
    #pragma unroll
    for (int i = 0; i < 4; i++) { l[i] = dec_f(g_att_u[tid * 4 + i]); m = fmaxf(m, l[i]); }
    #pragma unroll
    for (int o = 16; o; o >>= 1) m = fmaxf(m, __shfl_xor_sync(0xffffffffu, m, o));
    if ((tid & 31) == 0) red[tid >> 5] = m;
    __syncthreads();
    if (tid < 32) {
        float v = red[tid];
        #pragma unroll
        for (int o = 16; o; o >>= 1) v = fmaxf(v, __shfl_xor_sync(0xffffffffu, v, o));
        if (tid == 0) bval = v;
    }
    __syncthreads();
    float M = bval;
    float e[4], s = 0.0f;
    #pragma unroll
    for (int i = 0; i < 4; i++) { e[i] = expf(l[i] - M); s += e[i]; }
    #pragma unroll
    for (int o = 16; o; o >>= 1) s += __shfl_xor_sync(0xffffffffu, s, o);
    if ((tid & 31) == 0) red[tid >> 5] = s;
    __syncthreads();
    if (tid < 32) {
        float v = red[tid];
        #pragma unroll
        for (int o = 16; o; o >>= 1) v += __shfl_xor_sync(0xffffffffu, v, o);
        if (tid == 0) bval = v;
    }
    __syncthreads();
    float S = bval;
    #pragma unroll
    for (int i = 0; i < 4; i++) g_att[tid * 4 + i] = e[i] / S;
}

// ---------------- path_emb[j] = sum_p att[p]*h[p][j] ----------------
__global__ void pathemb_kernel() {
    __shared__ float s[256];
    int tid = threadIdx.x;
    int col = blockIdx.x * 32 + (tid & 31);
    int pg = tid >> 5;
    const __nv_bfloat16* h = g_hbufH[1];
    float acc = 0.0f;
    for (int p = pg * 512; p < pg * 512 + 512; p++)
        acc += g_att[p] * __bfloat162float(h[p * HID + col]);
    s[tid] = acc;
    __syncthreads();
    if (pg == 0) {
        float v = s[tid];
        #pragma unroll
        for (int k = 1; k < 8; k++) v += s[k * 32 + tid];
        g_pe[col] = v;
    }
}

// ---------------- final linear + sigmoid ----------------
__global__ void final_kernel(const float* __restrict__ emb, const float* __restrict__ w_lin,
                             const float* __restrict__ b_lin, const int* __restrict__ user_id,
                             const int* __restrict__ item_id, float* __restrict__ out) {
    __shared__ float red[8];
    int tid = threadIdx.x;   // 256
    int u = user_id[0], it = item_id[0];
    float a = w_lin[tid] * emb[(size_t)u * DIM + tid]
            + w_lin[256 + tid] * emb[(size_t)it * DIM + tid]
            + w_lin[512 + tid] * g_pe[tid];
    #pragma unroll
    for (int o = 16; o; o >>= 1) a += __shfl_xor_sync(0xffffffffu, a, o);
    if ((tid & 31) == 0) red[tid >> 5] = a;
    __syncthreads();
    if (tid == 0) {
        float s = 0.0f;
        #pragma unroll
        for (int k = 0; k < 8; k++) s += red[k];
        out[0] = 1.0f / (1.0f + expf(-(s + b_lin[0])));
    }
}

// ---------------- host ----------------
extern "C" void kernel_launch(void* const* d_in, const int* in_sizes, int n_in,
                              void* d_out, int out_size) {
    const float* emb   = (const float*)d_in[0];
    const float* w_ih  = (const float*)d_in[1];
    const float* w_hh  = (const float*)d_in[2];
    const float* b_ih  = (const float*)d_in[3];
    const float* b_hh  = (const float*)d_in[4];
    const float* w_lin = (const float*)d_in[5];
    const float* b_lin = (const float*)d_in[6];
    const int* paths   = (const int*)d_in[7];
    const int* uid     = (const int*)d_in[8];
    const int* iid     = (const int*)d_in[9];
    float* out = (float*)d_out;

    cudaFuncSetAttribute(gemm0_kernel, cudaFuncAttributeMaxDynamicSharedMemorySize, SMEM_G0);
    cudaFuncSetAttribute(rec_kernel, cudaFuncAttributeMaxDynamicSharedMemorySize, SMEM_REC2);

    prep_kernel<<<(NG * KDIM) / 256, 256>>>(w_ih, w_hh, b_ih, b_hh);
    gather_kernel<<<(LEN * PATHS * 64) / 256, 256>>>(emb, paths);

    // input projection for all 8 timesteps (M=32768); t==0 tiles do the step0 cell update inline
    gemm0_kernel<<<dim3(NG / BN, (LEN * PATHS) / BM), 256, SMEM_G0>>>();

    // steps 1..7 in ONE persistent kernel (128 CTAs x 512 threads, 1 CTA/SM)
    rec_kernel<<<R_CTAS, 512, SMEM_REC2>>>();

    softmax_kernel<<<1, 1024>>>();
    pathemb_kernel<<<HID / 32, 256>>>();
    final_kernel<<<1, 256>>>(emb, w_lin, b_lin, uid, iid, out);
}

// round 11
// speedup vs baseline: 1.9333x; 1.0029x over previous
#include <cuda_runtime.h>
#include <cuda_bf16.h>
#include <cstdint>
#include <math.h>

#define PATHS 4096
#define LEN 8
#define DIM 256
#define HID 256
#define NG 1024   // 4*HID
#define KDIM 256

#define BM 128
#define BN 128
#define BK 32            // halves per k-chunk
#define ROWSTR 40        // halves per A pipeline smem row (80B)
#define STAGEH ((BM + BN) * ROWSTR)          // halves per stage for gemm0
#define NSTAGE 4
#define SMEM_G0 (NSTAGE * STAGEH * 2)        // 81920 bytes
#define G0_OSTR 136                          // halves per staged-output row (272B, conflict-free)

// ---- persistent recurrence: 128 CTAs x 512 threads, BM=256 x BN=128, 1 CTA/SM ----
#define R_BM 256
#define R_BN 128
#define RSTR_B 264                            // halves per B row (528B)
#define R_ASTG (R_BM * ROWSTR * 2)            // 20480 B per A stage
#define R_SMB (3 * R_ASTG)                    // 61440: B tile offset
#define R_SMG (R_SMB + R_BN * RSTR_B * 2)     // 129024: Gin tile offset
#define R_GSTR 136                            // halves per Gin smem row (272B -> conflict-free)
#define SMEM_REC2 (R_SMG + R_BM * R_GSTR * 2) // 198656
#define R_CTAS 128
#define R_HSTR 40                             // halves per staged-h row (80B)

// ---------------- device scratch ----------------
__device__ __nv_bfloat16 g_GinH[(size_t)LEN * PATHS * NG];  // 64 MB precomputed input gates
__device__ __nv_bfloat16 g_x[(size_t)LEN * PATHS * DIM];    // 16 MB gathered+converted embeddings
__device__ __nv_bfloat16 g_WihH[NG * KDIM];                 // permuted bf16 w_ih (row 4j+q)
__device__ __nv_bfloat16 g_WhhH[NG * KDIM];                 // permuted bf16 w_hh
__device__ float g_bias[NG];
__device__ __nv_bfloat16 g_hbufH[2][PATHS * HID];
__device__ float g_cbuf[PATHS * HID];
__device__ unsigned g_att_u[PATHS];                         // monotonic-encoded float max
__device__ float g_att[PATHS];
__device__ float g_pe[HID];
__device__ unsigned g_cnt_g[16];                            // per-m-group barrier arrivals
__device__ volatile unsigned g_gen_g[16];                   // per-m-group barrier generation

// ---------------- helpers ----------------
__device__ __forceinline__ void cp16(uint32_t smem_dst, const void* gmem_src) {
    asm volatile("cp.async.cg.shared.global [%0], [%1], 16;\n" :: "r"(smem_dst), "l"(gmem_src));
}
__device__ __forceinline__ void cp_commit() { asm volatile("cp.async.commit_group;\n"); }
template <int N>
__device__ __forceinline__ void cp_wait() { asm volatile("cp.async.wait_group %0;\n" :: "n"(N)); }

__device__ __forceinline__ void ldsm4(uint32_t* r, uint32_t saddr) {
    asm volatile("ldmatrix.sync.aligned.m8n8.x4.shared.b16 {%0,%1,%2,%3}, [%4];\n"
                 : "=r"(r[0]), "=r"(r[1]), "=r"(r[2]), "=r"(r[3]) : "r"(saddr));
}
__device__ __forceinline__ void mma_bf16(float* c, const uint32_t* a, const uint32_t* b) {
    asm volatile(
        "mma.sync.aligned.m16n8k16.row.col.f32.bf16.bf16.f32 "
        "{%0,%1,%2,%3},{%4,%5,%6,%7},{%8,%9},{%0,%1,%2,%3};\n"
        : "+f"(c[0]), "+f"(c[1]), "+f"(c[2]), "+f"(c[3])
        : "r"(a[0]), "r"(a[1]), "r"(a[2]), "r"(a[3]), "r"(b[0]), "r"(b[1]));
}
__device__ __forceinline__ float sigf(float x) { return __fdividef(1.0f, 1.0f + __expf(-x)); }
__device__ __forceinline__ float tanh_fast(float x) {
    float e = __expf(2.0f * x);
    return 1.0f - __fdividef(2.0f, e + 1.0f);
}

__device__ __forceinline__ unsigned enc_f(float f) {
    unsigned b = __float_as_uint(f);
    return (b & 0x80000000u) ? ~b : (b | 0x80000000u);
}
__device__ __forceinline__ float dec_f(unsigned u) {
    unsigned b = (u & 0x80000000u) ? (u ^ 0x80000000u) : ~u;
    return __uint_as_float(b);
}

// ---------------- prep: weight permute + bf16, bias, barrier/att reset ----------------
__global__ void prep_kernel(const float* __restrict__ w_ih, const float* __restrict__ w_hh,
                            const float* __restrict__ b_ih, const float* __restrict__ b_hh) {
    int idx = blockIdx.x * blockDim.x + threadIdx.x;
    if (idx < NG * KDIM) {
        int r = idx >> 8;
        int k = idx & 255;
        int j = r >> 2, q = r & 3;
        int src = (q * HID + j) * KDIM + k;
        g_WihH[idx] = __float2bfloat16(w_ih[src]);
        g_WhhH[idx] = __float2bfloat16(w_hh[src]);
        if (k == 0) g_bias[r] = b_ih[q * HID + j] + b_hh[q * HID + j];
    }
    if (idx < PATHS) g_att_u[idx] = 0u;
    if (idx < 16) { g_cnt_g[idx] = 0u; g_gen_g[idx] = 0u; }
}

// ---------------- embedding gather + bf16 convert ----------------
__global__ void gather_kernel(const float* __restrict__ emb, const int* __restrict__ paths) {
    int idx = blockIdx.x * blockDim.x + threadIdx.x;  // over 32768*64 float4 units
    int m = idx >> 6;
    int ch = idx & 63;
    int p = m & 4095, t = m >> 12;
    int node = paths[p * LEN + t];
    float4 v = *(const float4*)(emb + (size_t)node * DIM + ch * 4);
    __nv_bfloat162* dst = (__nv_bfloat162*)(g_x + (size_t)m * DIM + ch * 4);
    dst[0] = __floats2bfloat162_rn(v.x, v.y);
    dst[1] = __floats2bfloat162_rn(v.z, v.w);
}

// ---------------- input projection GEMM (all 8 timesteps), fused step0 for t==0 rows ------
__global__ void __launch_bounds__(256, 2)
gemm0_kernel() {
    extern __shared__ __nv_bfloat16 smem[];
    const uint32_t smem_u32 = (uint32_t)__cvta_generic_to_shared(smem);
    const int tid = threadIdx.x;
    const int m0 = blockIdx.y * BM;
    const int n0 = blockIdx.x * BN;

    const __nv_bfloat16* gsrc = (tid < 128) ? (g_x + (size_t)(m0 + tid) * KDIM)
                                            : (g_WihH + (size_t)(n0 + tid - 128) * KDIM);
    const uint32_t srow = smem_u32 + tid * (ROWSTR * 2);

    const int warp = tid >> 5, lane = tid & 31;
    const int wm = warp >> 1, wn = warp & 1;
    const int g = lane >> 2, t4 = lane & 3;

    const int li = lane & 7;
    const int a_row_off = ((lane >> 3) & 1) * 8 + li;
    const int a_k_off = (lane >> 4) * 8;
    const int b_row_off = ((lane >> 4) & 1) * 8 + li;
    const int b_k_off = ((lane >> 3) & 1) * 8;

    float acc[2][8][4];
    #pragma unroll
    for (int a = 0; a < 2; a++)
        #pragma unroll
        for (int b = 0; b < 8; b++)
            #pragma unroll
            for (int c = 0; c < 4; c++) acc[a][b][c] = 0.0f;

    #pragma unroll
    for (int s = 0; s < NSTAGE - 1; s++) {
        uint32_t dst = srow + s * (STAGEH * 2);
        const __nv_bfloat16* src = gsrc + s * BK;
        #pragma unroll
        for (int i = 0; i < 4; i++) cp16(dst + i * 16, src + i * 8);
        cp_commit();
    }

    #pragma unroll
    for (int kc = 0; kc < KDIM / BK; kc++) {
        if (kc < KDIM / BK - 2)      cp_wait<NSTAGE - 2>();
        else if (kc == KDIM / BK - 2) cp_wait<1>();
        else                          cp_wait<0>();
        __syncthreads();

        if (kc + NSTAGE - 1 < KDIM / BK) {
            int s = kc + NSTAGE - 1;
            uint32_t dst = srow + (s & (NSTAGE - 1)) * (STAGEH * 2);
            const __nv_bfloat16* src = gsrc + s * BK;
            #pragma unroll
            for (int i = 0; i < 4; i++) cp16(dst + i * 16, src + i * 8);
            cp_commit();
        }

        const uint32_t Abase = smem_u32 + (kc & (NSTAGE - 1)) * (STAGEH * 2);
        const uint32_t Bbase = Abase + BM * (ROWSTR * 2);

        #pragma unroll
        for (int s = 0; s < 2; s++) {
            const int kb = s * 16;
            uint32_t afr[2][4], bfr[4][4];
            #pragma unroll
            for (int mt = 0; mt < 2; mt++) {
                int rb = wm * 32 + mt * 16;
                ldsm4(afr[mt], Abase + (rb + a_row_off) * (ROWSTR * 2) + (kb + a_k_off) * 2);
            }
            #pragma unroll
            for (int u = 0; u < 4; u++) {
                int cb = wn * 64 + u * 16;
                ldsm4(bfr[u], Bbase + (cb + b_row_off) * (ROWSTR * 2) + (kb + b_k_off) * 2);
            }
            #pragma unroll
            for (int mt = 0; mt < 2; mt++)
                #pragma unroll
                for (int u = 0; u < 4; u++) {
                    mma_bf16(acc[mt][2 * u],     afr[mt], &bfr[u][0]);
                    mma_bf16(acc[mt][2 * u + 1], afr[mt], &bfr[u][2]);
                }
        }
    }

    if (m0 < PATHS) {
        // t == 0 rows: fused step0 cell update (c_old = h_old = 0)
        #pragma unroll
        for (int mt = 0; mt < 2; mt++) {
            #pragma unroll
            for (int nt = 0; nt < 8; nt++) {
                int row = m0 + wm * 32 + mt * 16 + g;
                int col = n0 + wn * 64 + nt * 8 + 2 * t4;
                float b0 = g_bias[col], b1 = g_bias[col + 1];
                float v0 = acc[mt][nt][0] + b0, v1 = acc[mt][nt][1] + b1;
                float v2 = acc[mt][nt][2] + b0, v3 = acc[mt][nt][3] + b1;
                float r0 = __shfl_xor_sync(0xffffffffu, v0, 1);
                float r1 = __shfl_xor_sync(0xffffffffu, v1, 1);
                float r2 = __shfl_xor_sync(0xffffffffu, v2, 1);
                float r3 = __shfl_xor_sync(0xffffffffu, v3, 1); (void)r3;
                float q0, q2, q3; int rr, j;
                if ((t4 & 1) == 0) {
                    q0 = v0; q2 = r0; q3 = r1; rr = row; j = col >> 2;
                } else {
                    q0 = r2; q2 = v2; q3 = v3; rr = row + 8; j = (col - 2) >> 2;
                }
                float ig = sigf(q0);
                float gg = tanh_fast(q2);
                float og = sigf(q3);
                float c = ig * gg;
                g_cbuf[rr * HID + j] = c;
                g_hbufH[0][rr * HID + j] = __float2bfloat16(og * tanh_fast(c));
            }
        }
    } else {
        // t > 0 rows: add bias, stage bf16 tile in smem, then coalesced store to GinH
        __syncthreads();   // all ldsm of last chunk done; pipeline smem reusable
        #pragma unroll
        for (int mt = 0; mt < 2; mt++) {
            #pragma unroll
            for (int nt = 0; nt < 8; nt++) {
                int rowl = wm * 32 + mt * 16 + g;
                int col = wn * 64 + nt * 8 + 2 * t4;
                float b0 = g_bias[n0 + col], b1 = g_bias[n0 + col + 1];
                *(__nv_bfloat162*)(smem + rowl * G0_OSTR + col) =
                    __floats2bfloat162_rn(acc[mt][nt][0] + b0, acc[mt][nt][1] + b1);
                *(__nv_bfloat162*)(smem + (rowl + 8) * G0_OSTR + col) =
                    __floats2bfloat162_rn(acc[mt][nt][2] + b0, acc[mt][nt][3] + b1);
            }
        }
        __syncthreads();
        // coalesced write: 128 rows x 256B; thread -> half a row (128B)
        int row = tid >> 1, part = tid & 1;
        const uint4* srcq = (const uint4*)(smem + row * G0_OSTR + part * 64);
        uint4* dstq = (uint4*)&g_GinH[(size_t)(m0 + row) * NG + n0 + part * 64];
        #pragma unroll
        for (int i = 0; i < 8; i++) dstq[i] = srcq[i];
    }
}

// ---------------- persistent recurrence: steps 1..7, 128 CTAs x 512 threads ----------------
// BM=256 x BN=128 per CTA, 1 CTA/SM. Whh persists in smem; Gin prefetched to smem; c in
// registers; h staged in smem then written coalesced; PER-M-GROUP barrier (8 CTAs).
__global__ void __launch_bounds__(512, 1)
rec_kernel() {
    extern __shared__ __nv_bfloat16 smem[];
    const uint32_t sb = (uint32_t)__cvta_generic_to_shared(smem);
    const int tid = threadIdx.x;
    const int mg = blockIdx.x >> 3;            // m-group (16 groups of 8 CTAs)
    const int m0 = mg * R_BM;
    const int n0 = (blockIdx.x & 7) * R_BN;

    const int warp = tid >> 5, lane = tid & 31;
    const int wm = warp >> 1, wn = warp & 1;     // 8 x 2 warps, warp tile 32 x 64
    const int g = lane >> 2, t4 = lane & 3;
    const int li = lane & 7;
    const int a_row_off = ((lane >> 3) & 1) * 8 + li;
    const int a_k_off = (lane >> 4) * 8;
    const int b_row_off = ((lane >> 4) & 1) * 8 + li;
    const int b_k_off = ((lane >> 3) & 1) * 8;

    // ---- persistent B tile: Whh rows n0..n0+127, full K (4096 x 16B chunks) ----
    #pragma unroll
    for (int kk = 0; kk < 8; kk++) {
        int idx = tid + kk * 512;
        int row = idx >> 5, ch = idx & 31;
        cp16(sb + R_SMB + row * (RSTR_B * 2) + ch * 16,
             g_WhhH + (size_t)(n0 + row) * KDIM + ch * 8);
    }
    // B commits together with first A stage of step 1 (group s0)

    // ---- initial c into registers; ownership fixed per thread ----
    float creg[16];
    const int odd = t4 & 1;
    const int rbase = wm * 32 + g + (odd ? 8 : 0);     // + mt*16
    const int jloc = wn * 16 + (t4 >> 1);              // local hidden col + 2*nt (0..31)
    #pragma unroll
    for (int mt = 0; mt < 2; mt++)
        #pragma unroll
        for (int nt = 0; nt < 8; nt++)
            creg[mt * 8 + nt] = g_cbuf[(m0 + rbase + mt * 16) * HID + (n0 >> 2) + jloc + 2 * nt];

    for (int t = 1; t < LEN; t++) {
        const __nv_bfloat16* asrc = g_hbufH[(t + 1) & 1] + (size_t)m0 * KDIM;
        const int arow = tid >> 1;
        const int aoff = (tid & 1) * 16;   // halves

        float acc[2][8][4];
        #pragma unroll
        for (int a = 0; a < 2; a++)
            #pragma unroll
            for (int b = 0; b < 8; b++)
                #pragma unroll
                for (int c = 0; c < 4; c++) acc[a][b][c] = 0.0f;

        // prologue: s0 (group 0, includes B at t==1), s1 (group 1), Gin (group 2)
        #pragma unroll
        for (int s = 0; s < 2; s++) {
            uint32_t dst = sb + s * R_ASTG + arow * (ROWSTR * 2) + aoff * 2;
            const __nv_bfloat16* src = asrc + arow * KDIM + s * BK + aoff;
            cp16(dst, src); cp16(dst + 16, src + 8);
            cp_commit();
        }
        {
            // Gin tile: 256 rows x 128 cols bf16 = 4096 x 16B chunks
            const __nv_bfloat16* gsrc = g_GinH + ((size_t)t * PATHS + m0) * NG + n0;
            #pragma unroll
            for (int kk = 0; kk < 8; kk++) {
                int idx = tid + kk * 512;
                int row = idx >> 4, ch = idx & 15;
                cp16(sb + R_SMG + row * (R_GSTR * 2) + ch * 16, gsrc + (size_t)row * NG + ch * 8);
            }
            cp_commit();
        }

        #pragma unroll
        for (int kc = 0; kc < KDIM / BK; kc++) {
            if (kc <= 1)      cp_wait<2>();
            else if (kc <= 6) cp_wait<1>();
            else              cp_wait<0>();
            __syncthreads();

            if (kc + 2 < KDIM / BK) {
                int s = kc + 2;
                uint32_t dst = sb + (s % 3) * R_ASTG + arow * (ROWSTR * 2) + aoff * 2;
                const __nv_bfloat16* src = asrc + arow * KDIM + s * BK + aoff;
                cp16(dst, src); cp16(dst + 16, src + 8);
                cp_commit();
            }

            const uint32_t Abase = sb + (kc % 3) * R_ASTG;
            const uint32_t Bbase = sb + R_SMB;

            #pragma unroll
            for (int s = 0; s < 2; s++) {
                const int kb = s * 16;
                const int kT = kc * BK;
                uint32_t afr[2][4], bfr[4][4];
                #pragma unroll
                for (int mt = 0; mt < 2; mt++) {
                    int rb = wm * 32 + mt * 16;
                    ldsm4(afr[mt], Abase + (rb + a_row_off) * (ROWSTR * 2) + (kb + a_k_off) * 2);
                }
                #pragma unroll
                for (int u = 0; u < 4; u++) {
                    int cb = wn * 64 + u * 16;
                    ldsm4(bfr[u], Bbase + (cb + b_row_off) * (RSTR_B * 2) + (kT + kb + b_k_off) * 2);
                }
                #pragma unroll
                for (int mt = 0; mt < 2; mt++)
                    #pragma unroll
                    for (int u = 0; u < 4; u++) {
                        mma_bf16(acc[mt][2 * u],     afr[mt], &bfr[u][0]);
                        mma_bf16(acc[mt][2 * u + 1], afr[mt], &bfr[u][2]);
                    }
            }
        }

        // ---- fused LSTM cell epilogue (registers), then staged coalesced h store ----
        float hreg[16];
        #pragma unroll
        for (int mt = 0; mt < 2; mt++) {
            float hmax = -1e30f;
            #pragma unroll
            for (int nt = 0; nt < 8; nt++) {
                int rowA = wm * 32 + mt * 16 + g;            // local row of v0/v1
                int cl = wn * 64 + nt * 8 + 2 * t4;          // local col of v0
                const char* gb = (const char*)smem + R_SMG;
                __nv_bfloat162 g0 = *(const __nv_bfloat162*)(gb + rowA * (R_GSTR * 2) + cl * 2);
                __nv_bfloat162 g1 = *(const __nv_bfloat162*)(gb + (rowA + 8) * (R_GSTR * 2) + cl * 2);
                float v0 = acc[mt][nt][0] + __bfloat162float(g0.x);
                float v1 = acc[mt][nt][1] + __bfloat162float(g0.y);
                float v2 = acc[mt][nt][2] + __bfloat162float(g1.x);
                float v3 = acc[mt][nt][3] + __bfloat162float(g1.y);
                float r0 = __shfl_xor_sync(0xffffffffu, v0, 1);
                float r1 = __shfl_xor_sync(0xffffffffu, v1, 1);
                float r2 = __shfl_xor_sync(0xffffffffu, v2, 1);
                float r3 = __shfl_xor_sync(0xffffffffu, v3, 1);
                float qi, qf, qg, qo;
                if (!odd) { qi = v0; qf = v1; qg = r0; qo = r1; }
                else      { qi = r2; qf = r3; qg = v2; qo = v3; }
                float ig = sigf(qi);
                float fg = sigf(qf);
                float gg = tanh_fast(qg);
                float og = sigf(qo);
                float c = fg * creg[mt * 8 + nt] + ig * gg;
                creg[mt * 8 + nt] = c;
                float h = og * tanh_fast(c);
                hreg[mt * 8 + nt] = h;
                hmax = fmaxf(hmax, h);
            }
            if (t == LEN - 1) {
                // combine t4 pairs {0,2} / {1,3} (same row, complementary j sets)
                hmax = fmaxf(hmax, __shfl_xor_sync(0xffffffffu, hmax, 2));
                if (t4 < 2) atomicMax(&g_att_u[m0 + rbase + mt * 16], enc_f(hmax));
            }
        }

        // stage h tile (256 x 32 bf16) in A-pipeline smem region, then coalesced STG
        __syncthreads();   // all ldsm of last chunk retired; A region reusable
        #pragma unroll
        for (int mt = 0; mt < 2; mt++)
            #pragma unroll
            for (int nt = 0; nt < 8; nt++)
                smem[(rbase + mt * 16) * R_HSTR + jloc + 2 * nt] = __float2bfloat16(hreg[mt * 8 + nt]);
        __syncthreads();
        {
            __nv_bfloat16* hout = g_hbufH[t & 1];
            int row = tid >> 1, part = tid & 1;
            const uint4* srcq = (const uint4*)(smem + row * R_HSTR + part * 16);
            uint4* dstq = (uint4*)&hout[(size_t)(m0 + row) * HID + (n0 >> 2) + part * 16];
            dstq[0] = srcq[0];
            dstq[1] = srcq[1];
        }

        // ---- per-m-group barrier (8 CTAs share this m-tile) ----
        __threadfence();
        __syncthreads();
        if (tid == 0) {
            unsigned old = atomicAdd(&g_cnt_g[mg], 1u);
            if (old == (unsigned)(t * 8 - 1)) {
                __threadfence();
                g_gen_g[mg] = (unsigned)t;
            }
            while (g_gen_g[mg] < (unsigned)t) { }
            __threadfence();
        }
        __syncthreads();
    }
}

// ---------------- softmax over 4096 paths (single block, decodes att encoding) ----------------
__global__ void softmax_kernel() {
    __shared__ float red[32];
    __shared__ float bval;
    int tid = threadIdx.x;        // 1024 threads
    float l[4];
    float m = -1e30f;
    #pragma unroll
    for (int i = 0; i < 4; i++) { l[i] = dec_f(g_att_u[tid * 4 + i]); m = fmaxf(m, l[i]); }
    #pragma unroll
    for (int o = 16; o; o >>= 1) m = fmaxf(m, __shfl_xor_sync(0xffffffffu, m, o));
    if ((tid & 31) == 0) red[tid >> 5] = m;
    __syncthreads();
    if (tid < 32) {
        float v = red[tid];
        #pragma unroll
        for (int o = 16; o; o >>= 1) v = fmaxf(v, __shfl_xor_sync(0xffffffffu, v, o));
        if (tid == 0) bval = v;
    }
    __syncthreads();
    float M = bval;
    float e[4], s = 0.0f;
    #pragma unroll
    for (int i = 0; i < 4; i++) { e[i] = expf(l[i] - M); s += e[i]; }
    #pragma unroll
    for (int o = 16; o; o >>= 1) s += __shfl_xor_sync(0xffffffffu, s, o);
    if ((tid & 31) == 0) red[tid >> 5] = s;
    __syncthreads();
    if (tid < 32) {
        float v = red[tid];
        #pragma unroll
        for (int o = 16; o; o >>= 1) v += __shfl_xor_sync(0xffffffffu, v, o);
        if (tid == 0) bval = v;
    }
    __syncthreads();
    float S = bval;
    #pragma unroll
    for (int i = 0; i < 4; i++) g_att[tid * 4 + i] = e[i] / S;
}

// ---------------- path_emb[j] = sum_p att[p]*h[p][j] ----------------
__global__ void pathemb_kernel() {
    __shared__ float s[256];
    int tid = threadIdx.x;
    int col = blockIdx.x * 32 + (tid & 31);
    int pg = tid >> 5;
    const __nv_bfloat16* h = g_hbufH[1];
    float acc = 0.0f;
    for (int p = pg * 512; p < pg * 512 + 512; p++)
        acc += g_att[p] * __bfloat162float(h[p * HID + col]);
    s[tid] = acc;
    __syncthreads();
    if (pg == 0) {
        float v = s[tid];
        #pragma unroll
        for (int k = 1; k < 8; k++) v += s[k * 32 + tid];
        g_pe[col] = v;
    }
}

// ---------------- final linear + sigmoid ----------------
__global__ void final_kernel(const float* __restrict__ emb, const float* __restrict__ w_lin,
                             const float* __restrict__ b_lin, const int* __restrict__ user_id,
                             const int* __restrict__ item_id, float* __restrict__ out) {
    __shared__ float red[8];
    int tid = threadIdx.x;   // 256
    int u = user_id[0], it = item_id[0];
    float a = w_lin[tid] * emb[(size_t)u * DIM + tid]
            + w_lin[256 + tid] * emb[(size_t)it * DIM + tid]
            + w_lin[512 + tid] * g_pe[tid];
    #pragma unroll
    for (int o = 16; o; o >>= 1) a += __shfl_xor_sync(0xffffffffu, a, o);
    if ((tid & 31) == 0) red[tid >> 5] = a;
    __syncthreads();
    if (tid == 0) {
        float s = 0.0f;
        #pragma unroll
        for (int k = 0; k < 8; k++) s += red[k];
        out[0] = 1.0f / (1.0f + expf(-(s + b_lin[0])));
    }
}

// ---------------- host ----------------
extern "C" void kernel_launch(void* const* d_in, const int* in_sizes, int n_in,
                              void* d_out, int out_size) {
    const float* emb   = (const float*)d_in[0];
    const float* w_ih  = (const float*)d_in[1];
    const float* w_hh  = (const float*)d_in[2];
    const float* b_ih  = (const float*)d_in[3];
    const float* b_hh  = (const float*)d_in[4];
    const float* w_lin = (const float*)d_in[5];
    const float* b_lin = (const float*)d_in[6];
    const int* paths   = (const int*)d_in[7];
    const int* uid     = (const int*)d_in[8];
    const int* iid     = (const int*)d_in[9];
    float* out = (float*)d_out;

    cudaFuncSetAttribute(gemm0_kernel, cudaFuncAttributeMaxDynamicSharedMemorySize, SMEM_G0);
    cudaFuncSetAttribute(rec_kernel, cudaFuncAttributeMaxDynamicSharedMemorySize, SMEM_REC2);

    prep_kernel<<<(NG * KDIM) / 256, 256>>>(w_ih, w_hh, b_ih, b_hh);
    gather_kernel<<<(LEN * PATHS * 64) / 256, 256>>>(emb, paths);

    // input projection for all 8 timesteps (M=32768); t==0 tiles do the step0 cell update inline
    gemm0_kernel<<<dim3(NG / BN, (LEN * PATHS) / BM), 256, SMEM_G0>>>();

    // steps 1..7 in ONE persistent kernel (128 CTAs x 512 threads, per-m-group barriers)
    rec_kernel<<<R_CTAS, 512, SMEM_REC2>>>();

    softmax_kernel<<<1, 1024>>>();
    pathemb_kernel<<<HID / 32, 256>>>();
    final_kernel<<<1, 256>>>(emb, w_lin, b_lin, uid, iid, out);
}

// round 12
// speedup vs baseline: 2.6656x; 1.3787x over previous
#include <cuda_runtime.h>
#include <cuda_bf16.h>
#include <cstdint>
#include <math.h>

#define PATHS 4096
#define LEN 8
#define DIM 256
#define HID 256
#define NG 1024   // 4*HID
#define KDIM 256
#define BK 32            // halves per k-chunk
#define ROWSTR 40        // halves per A-stage / h-staging smem row (80B)

// ---- fused LSTM: 128 CTAs x 512 threads, BM=256 x BN=128, 1 CTA/SM ----
#define R_BM 256
#define R_BN 128
#define RSTR_B 264                            // halves per W row (528B)
#define R_ASTG (R_BM * ROWSTR * 2)            // 20480 B per A stage (3 stages)
#define W_OFF (3 * R_ASTG)                    // 61440: Wih tile
#define WHH_OFF (W_OFF + R_BN * RSTR_B * 2)   // 129024: Whh tile
#define H_OFF (WHH_OFF + R_BN * RSTR_B * 2)   // 196608: h staging (256 x 40 halves)
#define BIAS_OFF (H_OFF + R_BM * ROWSTR * 2)  // 217088: bias (128 floats)
#define SMEM_LSTM (BIAS_OFF + 512)            // 217600
#define R_CTAS 128

// ---------------- device scratch ----------------
__device__ __nv_bfloat16 g_x[(size_t)LEN * PATHS * DIM];    // 16 MB gathered+converted embeddings
__device__ __nv_bfloat16 g_WihH[NG * KDIM];                 // permuted bf16 w_ih (row 4j+q)
__device__ __nv_bfloat16 g_WhhH[NG * KDIM];                 // permuted bf16 w_hh
__device__ float g_bias[NG];
__device__ __nv_bfloat16 g_hbufH[2][PATHS * HID];
__device__ unsigned g_att_u[PATHS];                         // monotonic-encoded float max
__device__ float g_att[PATHS];
__device__ float g_pe[HID];
__device__ unsigned g_cnt_g[16];                            // per-m-group barrier arrivals
__device__ volatile unsigned g_gen_g[16];                   // per-m-group barrier generation

// ---------------- helpers ----------------
__device__ __forceinline__ void cp16(uint32_t smem_dst, const void* gmem_src) {
    asm volatile("cp.async.cg.shared.global [%0], [%1], 16;\n" :: "r"(smem_dst), "l"(gmem_src));
}
__device__ __forceinline__ void cp_commit() { asm volatile("cp.async.commit_group;\n"); }
template <int N>
__device__ __forceinline__ void cp_wait() { asm volatile("cp.async.wait_group %0;\n" :: "n"(N)); }

__device__ __forceinline__ void ldsm4(uint32_t* r, uint32_t saddr) {
    asm volatile("ldmatrix.sync.aligned.m8n8.x4.shared.b16 {%0,%1,%2,%3}, [%4];\n"
                 : "=r"(r[0]), "=r"(r[1]), "=r"(r[2]), "=r"(r[3]) : "r"(saddr));
}
__device__ __forceinline__ void mma_bf16(float* c, const uint32_t* a, const uint32_t* b) {
    asm volatile(
        "mma.sync.aligned.m16n8k16.row.col.f32.bf16.bf16.f32 "
        "{%0,%1,%2,%3},{%4,%5,%6,%7},{%8,%9},{%0,%1,%2,%3};\n"
        : "+f"(c[0]), "+f"(c[1]), "+f"(c[2]), "+f"(c[3])
        : "r"(a[0]), "r"(a[1]), "r"(a[2]), "r"(a[3]), "r"(b[0]), "r"(b[1]));
}
__device__ __forceinline__ float sigf(float x) { return __fdividef(1.0f, 1.0f + __expf(-x)); }
__device__ __forceinline__ float tanh_fast(float x) {
    float e = __expf(2.0f * x);
    return 1.0f - __fdividef(2.0f, e + 1.0f);
}
__device__ __forceinline__ unsigned enc_f(float f) {
    unsigned b = __float_as_uint(f);
    return (b & 0x80000000u) ? ~b : (b | 0x80000000u);
}
__device__ __forceinline__ float dec_f(unsigned u) {
    unsigned b = (u & 0x80000000u) ? (u ^ 0x80000000u) : ~u;
    return __uint_as_float(b);
}

// ---------------- prep: weight permute + bf16, bias, barrier/att reset ----------------
__global__ void prep_kernel(const float* __restrict__ w_ih, const float* __restrict__ w_hh,
                            const float* __restrict__ b_ih, const float* __restrict__ b_hh) {
    int idx = blockIdx.x * blockDim.x + threadIdx.x;
    if (idx < NG * KDIM) {
        int r = idx >> 8;
        int k = idx & 255;
        int j = r >> 2, q = r & 3;
        int src = (q * HID + j) * KDIM + k;
        g_WihH[idx] = __float2bfloat16(w_ih[src]);
        g_WhhH[idx] = __float2bfloat16(w_hh[src]);
        if (k == 0) g_bias[r] = b_ih[q * HID + j] + b_hh[q * HID + j];
    }
    if (idx < PATHS) g_att_u[idx] = 0u;
    if (idx < 16) { g_cnt_g[idx] = 0u; g_gen_g[idx] = 0u; }
}

// ---------------- embedding gather + bf16 convert ----------------
__global__ void gather_kernel(const float* __restrict__ emb, const int* __restrict__ paths) {
    int idx = blockIdx.x * blockDim.x + threadIdx.x;  // over 32768*64 float4 units
    int m = idx >> 6;
    int ch = idx & 63;
    int p = m & 4095, t = m >> 12;
    int node = paths[p * LEN + t];
    float4 v = *(const float4*)(emb + (size_t)node * DIM + ch * 4);
    __nv_bfloat162* dst = (__nv_bfloat162*)(g_x + (size_t)m * DIM + ch * 4);
    dst[0] = __floats2bfloat162_rn(v.x, v.y);
    dst[1] = __floats2bfloat162_rn(v.z, v.w);
}

// ---------------- one LSTM step mainloop: gates = [x | h] @ [Wih; Whh]^T ----------------
// KCH = 8 (t=0, x only) or 16 (x then h). On entry: 2 A-chunk groups outstanding
// (plus the weights group at t=0, retired by the first wait<1>).
template <int KCH>
__device__ __forceinline__ void do_step(
    uint32_t sb, const __nv_bfloat16* xsrc, const __nv_bfloat16* hsrc,
    int tid, int wm, int wn,
    int a_row_off, int a_k_off, int b_row_off, int b_k_off,
    float (&acc)[2][8][4])
{
    const int arow = tid >> 1;
    const int aoff = (tid & 1) * 16;
    #pragma unroll
    for (int kc = 0; kc < KCH; kc++) {
        if (kc < KCH - 1) cp_wait<1>(); else cp_wait<0>();
        __syncthreads();

        if (kc + 2 < KCH) {
            int s = kc + 2;
            uint32_t dst = sb + (s % 3) * R_ASTG + arow * (ROWSTR * 2) + aoff * 2;
            const __nv_bfloat16* src = (s < 8 ? xsrc + s * BK : hsrc + (s - 8) * BK)
                                       + arow * KDIM + aoff;
            cp16(dst, src); cp16(dst + 16, src + 8);
            cp_commit();
        }

        const uint32_t Abase = sb + (kc % 3) * R_ASTG;
        const uint32_t Bbase = sb + ((KCH == 16 && kc >= 8) ? WHH_OFF : W_OFF);
        const int kT = (kc & 7) * BK;

        #pragma unroll
        for (int s2 = 0; s2 < 2; s2++) {
            const int kb = s2 * 16;
            uint32_t afr[2][4], bfr[4][4];
            #pragma unroll
            for (int mt = 0; mt < 2; mt++) {
                int rb = wm * 32 + mt * 16;
                ldsm4(afr[mt], Abase + (rb + a_row_off) * (ROWSTR * 2) + (kb + a_k_off) * 2);
            }
            #pragma unroll
            for (int u = 0; u < 4; u++) {
                int cb = wn * 64 + u * 16;
                ldsm4(bfr[u], Bbase + (cb + b_row_off) * (RSTR_B * 2) + (kT + kb + b_k_off) * 2);
            }
            #pragma unroll
            for (int mt = 0; mt < 2; mt++)
                #pragma unroll
                for (int u = 0; u < 4; u++) {
                    mma_bf16(acc[mt][2 * u],     afr[mt], &bfr[u][0]);
                    mma_bf16(acc[mt][2 * u + 1], afr[mt], &bfr[u][2]);
                }
        }
    }
}

// ---------------- fused LSTM: all 8 steps + input projection + cell + att-max ----------------
__global__ void __launch_bounds__(512, 1)
lstm_kernel() {
    extern __shared__ __nv_bfloat16 smem[];
    char* smc = (char*)smem;
    const uint32_t sb = (uint32_t)__cvta_generic_to_shared(smem);
    const int tid = threadIdx.x;
    const int mg = blockIdx.x >> 3;            // m-group (16 groups of 8 CTAs)
    const int m0 = mg * R_BM;
    const int n0 = (blockIdx.x & 7) * R_BN;

    const int warp = tid >> 5, lane = tid & 31;
    const int wm = warp >> 1, wn = warp & 1;     // 8 x 2 warps, warp tile 32 x 64
    const int g = lane >> 2, t4 = lane & 3;
    const int li = lane & 7;
    const int a_row_off = ((lane >> 3) & 1) * 8 + li;
    const int a_k_off = (lane >> 4) * 8;
    const int b_row_off = ((lane >> 4) & 1) * 8 + li;
    const int b_k_off = ((lane >> 3) & 1) * 8;

    // ---- persistent weight tiles: Wih + Whh rows n0..n0+127 (one cp group) ----
    #pragma unroll
    for (int kk = 0; kk < 8; kk++) {
        int idx = tid + kk * 512;
        int row = idx >> 5, ch = idx & 31;
        cp16(sb + W_OFF + row * (RSTR_B * 2) + ch * 16,
             g_WihH + (size_t)(n0 + row) * KDIM + ch * 8);
        cp16(sb + WHH_OFF + row * (RSTR_B * 2) + ch * 16,
             g_WhhH + (size_t)(n0 + row) * KDIM + ch * 8);
    }
    cp_commit();

    float* s_bias = (float*)(smc + BIAS_OFF);
    if (tid < 128) s_bias[tid] = g_bias[n0 + tid];

    // ---- prologue: chunks 0,1 of x(0) ----
    {
        const int arow = tid >> 1, aoff = (tid & 1) * 16;
        const __nv_bfloat16* xs = g_x + (size_t)m0 * KDIM;
        #pragma unroll
        for (int s = 0; s < 2; s++) {
            uint32_t dst = sb + s * R_ASTG + arow * (ROWSTR * 2) + aoff * 2;
            const __nv_bfloat16* src = xs + arow * KDIM + s * BK + aoff;
            cp16(dst, src); cp16(dst + 16, src + 8);
            cp_commit();
        }
    }

    const int odd = t4 & 1;
    const int rbase = wm * 32 + g + (odd ? 8 : 0);     // + mt*16
    const int jloc = wn * 16 + (t4 >> 1);              // + 2*nt (0..31)
    __nv_bfloat16* s_h = smem + H_OFF / 2;

    float creg[16];
    #pragma unroll
    for (int i = 0; i < 16; i++) creg[i] = 0.0f;       // c_{-1} = 0 (f*0 = 0 at t=0)

    for (int t = 0; t < LEN; t++) {
        const __nv_bfloat16* xsrc = g_x + ((size_t)t * PATHS + m0) * KDIM;
        const __nv_bfloat16* hsrc = g_hbufH[(t + 1) & 1] + (size_t)m0 * KDIM;

        float acc[2][8][4];
        #pragma unroll
        for (int a = 0; a < 2; a++)
            #pragma unroll
            for (int b = 0; b < 8; b++)
                #pragma unroll
                for (int c = 0; c < 4; c++) acc[a][b][c] = 0.0f;

        if (t == 0) do_step<8>(sb, xsrc, hsrc, tid, wm, wn,
                               a_row_off, a_k_off, b_row_off, b_k_off, acc);
        else        do_step<16>(sb, xsrc, hsrc, tid, wm, wn,
                               a_row_off, a_k_off, b_row_off, b_k_off, acc);

        __syncthreads();   // all ldsm of the last stages retired; A region reusable

        // ---- prefetch chunks 0,1 of x(t+1) (barrier-independent) ----
        if (t + 1 < LEN) {
            const int arow = tid >> 1, aoff = (tid & 1) * 16;
            const __nv_bfloat16* xs = g_x + ((size_t)(t + 1) * PATHS + m0) * KDIM;
            #pragma unroll
            for (int s = 0; s < 2; s++) {
                uint32_t dst = sb + s * R_ASTG + arow * (ROWSTR * 2) + aoff * 2;
                const __nv_bfloat16* src = xs + arow * KDIM + s * BK + aoff;
                cp16(dst, src); cp16(dst + 16, src + 8);
                cp_commit();
            }
        }

        // ---- fused LSTM cell epilogue (registers + bias from smem, shfl-pair quads) ----
        #pragma unroll
        for (int mt = 0; mt < 2; mt++) {
            float hmax = -1e30f;
            #pragma unroll
            for (int nt = 0; nt < 8; nt++) {
                int cl = wn * 64 + nt * 8 + 2 * t4;          // local col of v0
                float b0 = s_bias[cl], b1 = s_bias[cl + 1];
                float v0 = acc[mt][nt][0] + b0;
                float v1 = acc[mt][nt][1] + b1;
                float v2 = acc[mt][nt][2] + b0;
                float v3 = acc[mt][nt][3] + b1;
                float r0 = __shfl_xor_sync(0xffffffffu, v0, 1);
                float r1 = __shfl_xor_sync(0xffffffffu, v1, 1);
                float r2 = __shfl_xor_sync(0xffffffffu, v2, 1);
                float r3 = __shfl_xor_sync(0xffffffffu, v3, 1);
                float qi, qf, qg, qo;
                if (!odd) { qi = v0; qf = v1; qg = r0; qo = r1; }
                else      { qi = r2; qf = r3; qg = v2; qo = v3; }
                float ig = sigf(qi);
                float fg = sigf(qf);
                float gg = tanh_fast(qg);
                float og = sigf(qo);
                float c = fg * creg[mt * 8 + nt] + ig * gg;
                creg[mt * 8 + nt] = c;
                float h = og * tanh_fast(c);
                s_h[(rbase + mt * 16) * ROWSTR + jloc + 2 * nt] = __float2bfloat16(h);
                hmax = fmaxf(hmax, h);
            }
            if (t == LEN - 1) {
                hmax = fmaxf(hmax, __shfl_xor_sync(0xffffffffu, hmax, 2));
                if (t4 < 2) atomicMax(&g_att_u[m0 + rbase + mt * 16], enc_f(hmax));
            }
        }

        // ---- coalesced h store from staging ----
        __syncthreads();
        {
            __nv_bfloat16* hout = g_hbufH[t & 1];
            int row = tid >> 1, part = tid & 1;
            const uint4* srcq = (const uint4*)(s_h + row * ROWSTR + part * 16);
            uint4* dstq = (uint4*)&hout[(size_t)(m0 + row) * HID + (n0 >> 2) + part * 16];
            dstq[0] = srcq[0];
            dstq[1] = srcq[1];
        }

        // ---- per-m-group barrier (8 CTAs share this m-tile) ----
        if (t + 1 < LEN) {
            __threadfence();
            __syncthreads();
            if (tid == 0) {
                unsigned old = atomicAdd(&g_cnt_g[mg], 1u);
                if (old == (unsigned)((t + 1) * 8 - 1)) {
                    __threadfence();
                    g_gen_g[mg] = (unsigned)(t + 1);
                }
                while (g_gen_g[mg] < (unsigned)(t + 1)) { }
                __threadfence();
            }
            __syncthreads();
        }
    }
}

// ---------------- softmax over 4096 paths (single block, decodes att encoding) ----------------
__global__ void softmax_kernel() {
    __shared__ float red[32];
    __shared__ float bval;
    int tid = threadIdx.x;        // 1024 threads
    float l[4];
    float m = -1e30f;
    #pragma unroll
    for (int i = 0; i < 4; i++) { l[i] = dec_f(g_att_u[tid * 4 + i]); m = fmaxf(m, l[i]); }
    #pragma unroll
    for (int o = 16; o; o >>= 1) m = fmaxf(m, __shfl_xor_sync(0xffffffffu, m, o));
    if ((tid & 31) == 0) red[tid >> 5] = m;
    __syncthreads();
    if (tid < 32) {
        float v = red[tid];
        #pragma unroll
        for (int o = 16; o; o >>= 1) v = fmaxf(v, __shfl_xor_sync(0xffffffffu, v, o));
        if (tid == 0) bval = v;
    }
    __syncthreads();
    float M = bval;
    float e[4], s = 0.0f;
    #pragma unroll
    for (int i = 0; i < 4; i++) { e[i] = expf(l[i] - M); s += e[i]; }
    #pragma unroll
    for (int o = 16; o; o >>= 1) s += __shfl_xor_sync(0xffffffffu, s, o);
    if ((tid & 31) == 0) red[tid >> 5] = s;
    __syncthreads();
    if (tid < 32) {
        float v = red[tid];
        #pragma unroll
        for (int o = 16; o; o >>= 1) v += __shfl_xor_sync(0xffffffffu, v, o);
        if (tid == 0) bval = v;
    }
    __syncthreads();
    float S = bval;
    #pragma unroll
    for (int i = 0; i < 4; i++) g_att[tid * 4 + i] = e[i] / S;
}

// ---------------- path_emb[j] = sum_p att[p]*h[p][j] ----------------
__global__ void pathemb_kernel() {
    __shared__ float s[256];
    int tid = threadIdx.x;
    int col = blockIdx.x * 32 + (tid & 31);
    int pg = tid >> 5;
    const __nv_bfloat16* h = g_hbufH[1];
    float acc = 0.0f;
    for (int p = pg * 512; p < pg * 512 + 512; p++)
        acc += g_att[p] * __bfloat162float(h[p * HID + col]);
    s[tid] = acc;
    __syncthreads();
    if (pg == 0) {
        float v = s[tid];
        #pragma unroll
        for (int k = 1; k < 8; k++) v += s[k * 32 + tid];
        g_pe[col] = v;
    }
}

// ---------------- final linear + sigmoid ----------------
__global__ void final_kernel(const float* __restrict__ emb, const float* __restrict__ w_lin,
                             const float* __restrict__ b_lin, const int* __restrict__ user_id,
                             const int* __restrict__ item_id, float* __restrict__ out) {
    __shared__ float red[8];
    int tid = threadIdx.x;   // 256
    int u = user_id[0], it = item_id[0];
    float a = w_lin[tid] * emb[(size_t)u * DIM + tid]
            + w_lin[256 + tid] * emb[(size_t)it * DIM + tid]
            + w_lin[512 + tid] * g_pe[tid];
    #pragma unroll
    for (int o = 16; o; o >>= 1) a += __shfl_xor_sync(0xffffffffu, a, o);
    if ((tid & 31) == 0) red[tid >> 5] = a;
    __syncthreads();
    if (tid == 0) {
        float s = 0.0f;
        #pragma unroll
        for (int k = 0; k < 8; k++) s += red[k];
        out[0] = 1.0f / (1.0f + expf(-(s + b_lin[0])));
    }
}

// ---------------- host ----------------
extern "C" void kernel_launch(void* const* d_in, const int* in_sizes, int n_in,
                              void* d_out, int out_size) {
    const float* emb   = (const float*)d_in[0];
    const float* w_ih  = (const float*)d_in[1];
    const float* w_hh  = (const float*)d_in[2];
    const float* b_ih  = (const float*)d_in[3];
    const float* b_hh  = (const float*)d_in[4];
    const float* w_lin = (const float*)d_in[5];
    const float* b_lin = (const float*)d_in[6];
    const int* paths   = (const int*)d_in[7];
    const int* uid     = (const int*)d_in[8];
    const int* iid     = (const int*)d_in[9];
    float* out = (float*)d_out;

    cudaFuncSetAttribute(lstm_kernel, cudaFuncAttributeMaxDynamicSharedMemorySize, SMEM_LSTM);

    prep_kernel<<<(NG * KDIM) / 256, 256>>>(w_ih, w_hh, b_ih, b_hh);
    gather_kernel<<<(LEN * PATHS * 64) / 256, 256>>>(emb, paths);

    // ALL 8 LSTM steps (input projection fused as K=512 GEMM) in one persistent kernel
    lstm_kernel<<<R_CTAS, 512, SMEM_LSTM>>>();

    softmax_kernel<<<1, 1024>>>();
    pathemb_kernel<<<HID / 32, 256>>>();
    final_kernel<<<1, 256>>>(emb, w_lin, b_lin, uid, iid, out);
}

// round 14
// speedup vs baseline: 2.8514x; 1.0697x over previous
#include <cuda_runtime.h>
#include <cuda_bf16.h>
#include <cstdint>
#include <math.h>

#define PATHS 4096
#define LEN 8
#define DIM 256
#define HID 256
#define NG 1024   // 4*HID
#define KDIM 256
#define BK 32            // halves per k-chunk
#define ROWSTR 40        // halves per A-stage / h-staging smem row (80B)

// ---- fused LSTM: 128 CTAs x 512 threads, BM=256 x BN=128, 1 CTA/SM ----
#define R_BM 256
#define R_BN 128
#define RSTR_B 264                            // halves per W row (528B)
#define R_ASTG (R_BM * ROWSTR * 2)            // 20480 B per A stage (3 stages)
#define W_OFF (3 * R_ASTG)                    // 61440: Wih tile
#define WHH_OFF (W_OFF + R_BN * RSTR_B * 2)   // 129024: Whh tile
#define H_OFF (WHH_OFF + R_BN * RSTR_B * 2)   // 196608: h staging (256 x 40 halves)
#define BIAS_OFF (H_OFF + R_BM * ROWSTR * 2)  // 217088: bias (128 floats)
#define SMEM_LSTM (BIAS_OFF + 512)            // 217600
#define R_CTAS 128

// ---------------- device scratch ----------------
__device__ __nv_bfloat16 g_x[(size_t)LEN * PATHS * DIM];    // 16 MB gathered+converted embeddings
__device__ __nv_bfloat16 g_WihH[NG * KDIM];                 // permuted bf16 w_ih (row 4j+q)
__device__ __nv_bfloat16 g_WhhH[NG * KDIM];                 // permuted bf16 w_hh
__device__ float g_bias[NG];
__device__ __nv_bfloat16 g_hbufH[2][PATHS * HID];
__device__ unsigned g_att_u[PATHS];                         // monotonic-encoded float max
__device__ float g_pe[HID];
__device__ unsigned g_cnt_g[16];                            // per-m-group barrier arrivals
__device__ volatile unsigned g_gen_g[16];                   // per-m-group barrier generation
__device__ unsigned g_done;                                 // tail last-block counter

// ---------------- helpers ----------------
__device__ __forceinline__ void cp16(uint32_t smem_dst, const void* gmem_src) {
    asm volatile("cp.async.cg.shared.global [%0], [%1], 16;\n" :: "r"(smem_dst), "l"(gmem_src));
}
__device__ __forceinline__ void cp_commit() { asm volatile("cp.async.commit_group;\n"); }
template <int N>
__device__ __forceinline__ void cp_wait() { asm volatile("cp.async.wait_group %0;\n" :: "n"(N)); }

__device__ __forceinline__ void ldsm4(uint32_t* r, uint32_t saddr) {
    asm volatile("ldmatrix.sync.aligned.m8n8.x4.shared.b16 {%0,%1,%2,%3}, [%4];\n"
                 : "=r"(r[0]), "=r"(r[1]), "=r"(r[2]), "=r"(r[3]) : "r"(saddr));
}
__device__ __forceinline__ void mma_bf16(float* c, const uint32_t* a, const uint32_t* b) {
    asm volatile(
        "mma.sync.aligned.m16n8k16.row.col.f32.bf16.bf16.f32 "
        "{%0,%1,%2,%3},{%4,%5,%6,%7},{%8,%9},{%0,%1,%2,%3};\n"
        : "+f"(c[0]), "+f"(c[1]), "+f"(c[2]), "+f"(c[3])
        : "r"(a[0]), "r"(a[1]), "r"(a[2]), "r"(a[3]), "r"(b[0]), "r"(b[1]));
}
__device__ __forceinline__ float sigf(float x) { return __fdividef(1.0f, 1.0f + __expf(-x)); }
__device__ __forceinline__ float tanh_fast(float x) {
    float e = __expf(2.0f * x);
    return 1.0f - __fdividef(2.0f, e + 1.0f);
}
__device__ __forceinline__ unsigned enc_f(float f) {
    unsigned b = __float_as_uint(f);
    return (b & 0x80000000u) ? ~b : (b | 0x80000000u);
}
__device__ __forceinline__ float dec_f(unsigned u) {
    unsigned b = (u & 0x80000000u) ? (u ^ 0x80000000u) : ~u;
    return __uint_as_float(b);
}

// ---------------- prep: weight permute + bf16, bias, barrier/att reset ----------------
__global__ void prep_kernel(const float* __restrict__ w_ih, const float* __restrict__ w_hh,
                            const float* __restrict__ b_ih, const float* __restrict__ b_hh) {
    int idx = blockIdx.x * blockDim.x + threadIdx.x;
    if (idx < NG * KDIM) {
        int r = idx >> 8;
        int k = idx & 255;
        int j = r >> 2, q = r & 3;
        int src = (q * HID + j) * KDIM + k;
        g_WihH[idx] = __float2bfloat16(w_ih[src]);
        g_WhhH[idx] = __float2bfloat16(w_hh[src]);
        if (k == 0) g_bias[r] = b_ih[q * HID + j] + b_hh[q * HID + j];
    }
    if (idx < PATHS) g_att_u[idx] = 0u;
    if (idx < 16) { g_cnt_g[idx] = 0u; g_gen_g[idx] = 0u; }
    if (idx == 16) g_done = 0u;
}

// ---------------- embedding gather + bf16 convert ----------------
__global__ void gather_kernel(const float* __restrict__ emb, const int* __restrict__ paths) {
    int idx = blockIdx.x * blockDim.x + threadIdx.x;  // over 32768*64 float4 units
    int m = idx >> 6;
    int ch = idx & 63;
    int p = m & 4095, t = m >> 12;
    int node = paths[p * LEN + t];
    float4 v = *(const float4*)(emb + (size_t)node * DIM + ch * 4);
    __nv_bfloat162* dst = (__nv_bfloat162*)(g_x + (size_t)m * DIM + ch * 4);
    dst[0] = __floats2bfloat162_rn(v.x, v.y);
    dst[1] = __floats2bfloat162_rn(v.z, v.w);
}

// ---------------- one K=256 GEMM part: acc += src @ W^T (8 chunks, self-contained) ----------
__device__ __forceinline__ void do_part(
    uint32_t sb, const __nv_bfloat16* src0, uint32_t woff,
    int tid, int wm, int wn,
    int a_row_off, int a_k_off, int b_row_off, int b_k_off,
    float (&acc)[2][8][4])
{
    const int arow = tid >> 1;
    const int aoff = (tid & 1) * 16;
    // prologue: chunks 0,1
    #pragma unroll
    for (int s = 0; s < 2; s++) {
        uint32_t dst = sb + s * R_ASTG + arow * (ROWSTR * 2) + aoff * 2;
        const __nv_bfloat16* src = src0 + arow * KDIM + s * BK + aoff;
        cp16(dst, src); cp16(dst + 16, src + 8);
        cp_commit();
    }
    #pragma unroll
    for (int kc = 0; kc < 8; kc++) {
        if (kc < 7) cp_wait<1>(); else cp_wait<0>();
        __syncthreads();

        if (kc + 2 < 8) {
            int s = kc + 2;
            uint32_t dst = sb + (s % 3) * R_ASTG + arow * (ROWSTR * 2) + aoff * 2;
            const __nv_bfloat16* src = src0 + arow * KDIM + s * BK + aoff;
            cp16(dst, src); cp16(dst + 16, src + 8);
            cp_commit();
        }

        const uint32_t Abase = sb + (kc % 3) * R_ASTG;
        const uint32_t Bbase = sb + woff;
        const int kT = kc * BK;

        #pragma unroll
        for (int s2 = 0; s2 < 2; s2++) {
            const int kb = s2 * 16;
            uint32_t afr[2][4], bfr[4][4];
            #pragma unroll
            for (int mt = 0; mt < 2; mt++) {
                int rb = wm * 32 + mt * 16;
                ldsm4(afr[mt], Abase + (rb + a_row_off) * (ROWSTR * 2) + (kb + a_k_off) * 2);
            }
            #pragma unroll
            for (int u = 0; u < 4; u++) {
                int cb = wn * 64 + u * 16;
                ldsm4(bfr[u], Bbase + (cb + b_row_off) * (RSTR_B * 2) + (kT + kb + b_k_off) * 2);
            }
            #pragma unroll
            for (int mt = 0; mt < 2; mt++)
                #pragma unroll
                for (int u = 0; u < 4; u++) {
                    mma_bf16(acc[mt][2 * u],     afr[mt], &bfr[u][0]);
                    mma_bf16(acc[mt][2 * u + 1], afr[mt], &bfr[u][2]);
                }
        }
    }
    __syncthreads();   // all ldsm of chunk 7 retired before stages are rewritten
}

// ---------------- fused LSTM: x-part of step t+1 overlapped with barrier wait ----------------
__global__ void __launch_bounds__(512, 1)
lstm_kernel() {
    extern __shared__ __nv_bfloat16 smem[];
    char* smc = (char*)smem;
    const uint32_t sb = (uint32_t)__cvta_generic_to_shared(smem);
    const int tid = threadIdx.x;
    const int mg = blockIdx.x >> 3;            // m-group (16 groups of 8 CTAs)
    const int m0 = mg * R_BM;
    const int n0 = (blockIdx.x & 7) * R_BN;

    const int warp = tid >> 5, lane = tid & 31;
    const int wm = warp >> 1, wn = warp & 1;     // 8 x 2 warps, warp tile 32 x 64
    const int g = lane >> 2, t4 = lane & 3;
    const int li = lane & 7;
    const int a_row_off = ((lane >> 3) & 1) * 8 + li;
    const int a_k_off = (lane >> 4) * 8;
    const int b_row_off = ((lane >> 4) & 1) * 8 + li;
    const int b_k_off = ((lane >> 3) & 1) * 8;

    // ---- persistent weight tiles: Wih + Whh rows n0..n0+127 (one cp group) ----
    #pragma unroll
    for (int kk = 0; kk < 8; kk++) {
        int idx = tid + kk * 512;
        int row = idx >> 5, ch = idx & 31;
        cp16(sb + W_OFF + row * (RSTR_B * 2) + ch * 16,
             g_WihH + (size_t)(n0 + row) * KDIM + ch * 8);
        cp16(sb + WHH_OFF + row * (RSTR_B * 2) + ch * 16,
             g_WhhH + (size_t)(n0 + row) * KDIM + ch * 8);
    }
    cp_commit();

    float* s_bias = (float*)(smc + BIAS_OFF);
    if (tid < 128) s_bias[tid] = g_bias[n0 + tid];

    const int odd = t4 & 1;
    const int rbase = wm * 32 + g + (odd ? 8 : 0);     // + mt*16
    const int jloc = wn * 16 + (t4 >> 1);              // + 2*nt (0..31)
    __nv_bfloat16* s_h = smem + H_OFF / 2;

    float creg[16];
    #pragma unroll
    for (int i = 0; i < 16; i++) creg[i] = 0.0f;       // c_{-1} = 0

    float acc[2][8][4];
    #pragma unroll
    for (int a = 0; a < 2; a++)
        #pragma unroll
        for (int b = 0; b < 8; b++)
            #pragma unroll
            for (int c = 0; c < 4; c++) acc[a][b][c] = 0.0f;

    // x-part of step 0 (weights group retired by first wait inside)
    do_part(sb, g_x + (size_t)m0 * KDIM, W_OFF,
            tid, wm, wn, a_row_off, a_k_off, b_row_off, b_k_off, acc);

    for (int t = 0; t < LEN; t++) {
        // ---- h-part: wait for h(t-1), then acc += h @ Whh^T ----
        if (t > 0) {
            if (tid == 0) {
                while (g_gen_g[mg] < (unsigned)t) { }
                __threadfence();
            }
            __syncthreads();
            do_part(sb, g_hbufH[(t + 1) & 1] + (size_t)m0 * KDIM, WHH_OFF,
                    tid, wm, wn, a_row_off, a_k_off, b_row_off, b_k_off, acc);
        }

        // ---- fused LSTM cell epilogue (registers + bias, shfl-pair quads) ----
        #pragma unroll
        for (int mt = 0; mt < 2; mt++) {
            float hmax = -1e30f;
            #pragma unroll
            for (int nt = 0; nt < 8; nt++) {
                int cl = wn * 64 + nt * 8 + 2 * t4;          // local col of v0
                float b0 = s_bias[cl], b1 = s_bias[cl + 1];
                float v0 = acc[mt][nt][0] + b0;
                float v1 = acc[mt][nt][1] + b1;
                float v2 = acc[mt][nt][2] + b0;
                float v3 = acc[mt][nt][3] + b1;
                float r0 = __shfl_xor_sync(0xffffffffu, v0, 1);
                float r1 = __shfl_xor_sync(0xffffffffu, v1, 1);
                float r2 = __shfl_xor_sync(0xffffffffu, v2, 1);
                float r3 = __shfl_xor_sync(0xffffffffu, v3, 1);
                float qi, qf, qg, qo;
                if (!odd) { qi = v0; qf = v1; qg = r0; qo = r1; }
                else      { qi = r2; qf = r3; qg = v2; qo = v3; }
                float ig = sigf(qi);
                float fg = sigf(qf);
                float gg = tanh_fast(qg);
                float og = sigf(qo);
                float c = fg * creg[mt * 8 + nt] + ig * gg;
                creg[mt * 8 + nt] = c;
                float h = og * tanh_fast(c);
                s_h[(rbase + mt * 16) * ROWSTR + jloc + 2 * nt] = __float2bfloat16(h);
                hmax = fmaxf(hmax, h);
            }
            if (t == LEN - 1) {
                hmax = fmaxf(hmax, __shfl_xor_sync(0xffffffffu, hmax, 2));
                if (t4 < 2) atomicMax(&g_att_u[m0 + rbase + mt * 16], enc_f(hmax));
            }
        }

        // ---- coalesced h store from staging ----
        __syncthreads();
        {
            __nv_bfloat16* hout = g_hbufH[t & 1];
            int row = tid >> 1, part = tid & 1;
            const uint4* srcq = (const uint4*)(s_h + row * ROWSTR + part * 16);
            uint4* dstq = (uint4*)&hout[(size_t)(m0 + row) * HID + (n0 >> 2) + part * 16];
            dstq[0] = srcq[0];
            dstq[1] = srcq[1];
        }

        if (t + 1 < LEN) {
            // ---- arrive (non-blocking) ----
            __threadfence();
            __syncthreads();
            if (tid == 0) {
                unsigned old = atomicAdd(&g_cnt_g[mg], 1u);
                if (old == (unsigned)((t + 1) * 8 - 1)) {
                    __threadfence();
                    g_gen_g[mg] = (unsigned)(t + 1);
                }
            }
            // ---- x-part of step t+1 (barrier-independent; overlaps others' stragglers) ----
            #pragma unroll
            for (int a = 0; a < 2; a++)
                #pragma unroll
                for (int b = 0; b < 8; b++)
                    #pragma unroll
                    for (int c = 0; c < 4; c++) acc[a][b][c] = 0.0f;
            do_part(sb, g_x + ((size_t)(t + 1) * PATHS + m0) * KDIM, W_OFF,
                    tid, wm, wn, a_row_off, a_k_off, b_row_off, b_k_off, acc);
        }
    }
}

// ---------------- fused tail: softmax (redundant per block) + pathemb + final ----------------
__global__ void tail_kernel(const float* __restrict__ emb, const float* __restrict__ w_lin,
                            const float* __restrict__ b_lin, const int* __restrict__ user_id,
                            const int* __restrict__ item_id, float* __restrict__ out) {
    __shared__ float s_att[PATHS];     // 16 KB
    __shared__ float s_part[256];
    __shared__ float red[8];
    __shared__ float s_red2;
    __shared__ int s_last;
    int tid = threadIdx.x;             // 256
    int wid = tid >> 5, lane = tid & 31;

    // block-local softmax over 4096 logits (16 per thread)
    float lv[16];
    float m = -1e30f;
    #pragma unroll
    for (int i = 0; i < 16; i++) {
        lv[i] = dec_f(g_att_u[tid * 16 + i]);
        m = fmaxf(m, lv[i]);
    }
    #pragma unroll
    for (int o = 16; o; o >>= 1) m = fmaxf(m, __shfl_xor_sync(0xffffffffu, m, o));
    if (lane == 0) red[wid] = m;
    __syncthreads();
    if (tid == 0) {
        float v = red[0];
        #pragma unroll
        for (int k = 1; k < 8; k++) v = fmaxf(v, red[k]);
        s_red2 = v;
    }
    __syncthreads();
    float M = s_red2;
    float s = 0.0f;
    #pragma unroll
    for (int i = 0; i < 16; i++) { lv[i] = __expf(lv[i] - M); s += lv[i]; }
    #pragma unroll
    for (int o = 16; o; o >>= 1) s += __shfl_xor_sync(0xffffffffu, s, o);
    if (lane == 0) red[wid] = s;
    __syncthreads();
    if (tid == 0) {
        float v = 0.0f;
        #pragma unroll
        for (int k = 0; k < 8; k++) v += red[k];
        s_red2 = v;
    }
    __syncthreads();
    float inv = __fdividef(1.0f, s_red2);
    #pragma unroll
    for (int i = 0; i < 16; i++) s_att[tid * 16 + i] = lv[i] * inv;
    __syncthreads();

    // pathemb: this block's 32 columns
    int col = blockIdx.x * 32 + (tid & 31);
    int pg = tid >> 5;
    const __nv_bfloat16* h = g_hbufH[1];
    float acc = 0.0f;
    for (int p = pg * 512; p < pg * 512 + 512; p++)
        acc += s_att[p] * __bfloat162float(h[p * HID + col]);
    s_part[tid] = acc;
    __syncthreads();
    if (pg == 0) {
        float v = s_part[tid];
        #pragma unroll
        for (int k = 1; k < 8; k++) v += s_part[k * 32 + tid];
        g_pe[col] = v;
    }
    __threadfence();
    __syncthreads();
    if (tid == 0) s_last = (atomicAdd(&g_done, 1u) == (unsigned)(gridDim.x - 1));
    __syncthreads();

    if (s_last) {
        __threadfence();   // acquire: all blocks' g_pe stores visible
        int u = user_id[0], it = item_id[0];
        float a = w_lin[tid] * emb[(size_t)u * DIM + tid]
                + w_lin[256 + tid] * emb[(size_t)it * DIM + tid]
                + w_lin[512 + tid] * g_pe[tid];
        #pragma unroll
        for (int o = 16; o; o >>= 1) a += __shfl_xor_sync(0xffffffffu, a, o);
        if (lane == 0) red[wid] = a;
        __syncthreads();
        if (tid == 0) {
            float sm = 0.0f;
            #pragma unroll
            for (int k = 0; k < 8; k++) sm += red[k];
            out[0] = 1.0f / (1.0f + expf(-(sm + b_lin[0])));
        }
    }
}

// ---------------- host ----------------
extern "C" void kernel_launch(void* const* d_in, const int* in_sizes, int n_in,
                              void* d_out, int out_size) {
    const float* emb   = (const float*)d_in[0];
    const float* w_ih  = (const float*)d_in[1];
    const float* w_hh  = (const float*)d_in[2];
    const float* b_ih  = (const float*)d_in[3];
    const float* b_hh  = (const float*)d_in[4];
    const float* w_lin = (const float*)d_in[5];
    const float* b_lin = (const float*)d_in[6];
    const int* paths   = (const int*)d_in[7];
    const int* uid     = (const int*)d_in[8];
    const int* iid     = (const int*)d_in[9];
    float* out = (float*)d_out;

    cudaFuncSetAttribute(lstm_kernel, cudaFuncAttributeMaxDynamicSharedMemorySize, SMEM_LSTM);

    prep_kernel<<<(NG * KDIM) / 256, 256>>>(w_ih, w_hh, b_ih, b_hh);
    gather_kernel<<<(LEN * PATHS * 64) / 256, 256>>>(emb, paths);

    // ALL 8 LSTM steps in one persistent kernel; x-part of t+1 overlaps the inter-step barrier
    lstm_kernel<<<R_CTAS, 512, SMEM_LSTM>>>();

    // fused softmax + pathemb + final
    tail_kernel<<<HID / 32, 256>>>(emb, w_lin, b_lin, uid, iid, out);
}

// round 15
// speedup vs baseline: 2.9354x; 1.0295x over previous
#include <cuda_runtime.h>
#include <cuda_bf16.h>
#include <cstdint>
#include <math.h>

#define PATHS 4096
#define LEN 8
#define DIM 256
#define HID 256
#define NG 1024   // 4*HID
#define KDIM 256
#define BK 32            // halves per k-chunk
#define ROWSTR 40        // halves per A-stage / h-staging smem row (80B)

// ---- fused LSTM: 128 CTAs x 512 threads, BM=256 x BN=128, 1 CTA/SM ----
#define R_BM 256
#define R_BN 128
#define RSTR_B 264                            // halves per W row (528B)
#define R_ASTG (R_BM * ROWSTR * 2)            // 20480 B per A stage (3 stages)
#define W_OFF (3 * R_ASTG)                    // 61440: Wih tile
#define WHH_OFF (W_OFF + R_BN * RSTR_B * 2)   // 129024: Whh tile
#define H_OFF (WHH_OFF + R_BN * RSTR_B * 2)   // 196608: h staging (256 x 40 halves)
#define BIAS_OFF (H_OFF + R_BM * ROWSTR * 2)  // 217088: bias (128 floats)
#define SMEM_LSTM (BIAS_OFF + 512)            // 217600
#define R_CTAS 128

// ---------------- device scratch ----------------
__device__ __nv_bfloat16 g_x[(size_t)LEN * PATHS * DIM];    // 16 MB gathered+converted embeddings
__device__ __nv_bfloat16 g_WihH[NG * KDIM];                 // permuted bf16 w_ih (row 4j+q)
__device__ __nv_bfloat16 g_WhhH[NG * KDIM];                 // permuted bf16 w_hh
__device__ float g_bias[NG];
__device__ __nv_bfloat16 g_hbufH[2][PATHS * HID];
__device__ unsigned g_att_u[PATHS];                         // monotonic-encoded float max
__device__ float g_att[PATHS];
__device__ float g_pe[HID];
__device__ unsigned g_cnt_g[16];                            // per-m-group barrier arrivals
__device__ volatile unsigned g_gen_g[16];                   // per-m-group barrier generation
__device__ unsigned g_done;                                 // tail last-block counter

// ---------------- helpers ----------------
__device__ __forceinline__ void cp16(uint32_t smem_dst, const void* gmem_src) {
    asm volatile("cp.async.cg.shared.global [%0], [%1], 16;\n" :: "r"(smem_dst), "l"(gmem_src));
}
__device__ __forceinline__ void cp_commit() { asm volatile("cp.async.commit_group;\n"); }
template <int N>
__device__ __forceinline__ void cp_wait() { asm volatile("cp.async.wait_group %0;\n" :: "n"(N)); }

__device__ __forceinline__ void ldsm4(uint32_t* r, uint32_t saddr) {
    asm volatile("ldmatrix.sync.aligned.m8n8.x4.shared.b16 {%0,%1,%2,%3}, [%4];\n"
                 : "=r"(r[0]), "=r"(r[1]), "=r"(r[2]), "=r"(r[3]) : "r"(saddr));
}
__device__ __forceinline__ void mma_bf16(float* c, const uint32_t* a, const uint32_t* b) {
    asm volatile(
        "mma.sync.aligned.m16n8k16.row.col.f32.bf16.bf16.f32 "
        "{%0,%1,%2,%3},{%4,%5,%6,%7},{%8,%9},{%0,%1,%2,%3};\n"
        : "+f"(c[0]), "+f"(c[1]), "+f"(c[2]), "+f"(c[3])
        : "r"(a[0]), "r"(a[1]), "r"(a[2]), "r"(a[3]), "r"(b[0]), "r"(b[1]));
}
__device__ __forceinline__ float sigf(float x) { return __fdividef(1.0f, 1.0f + __expf(-x)); }
__device__ __forceinline__ float tanh_fast(float x) {
    float e = __expf(2.0f * x);
    return 1.0f - __fdividef(2.0f, e + 1.0f);
}
__device__ __forceinline__ unsigned enc_f(float f) {
    unsigned b = __float_as_uint(f);
    return (b & 0x80000000u) ? ~b : (b | 0x80000000u);
}
__device__ __forceinline__ float dec_f(unsigned u) {
    unsigned b = (u & 0x80000000u) ? (u ^ 0x80000000u) : ~u;
    return __uint_as_float(b);
}

// ---------------- prep: weight permute + bf16, bias, barrier/att reset ----------------
__global__ void prep_kernel(const float* __restrict__ w_ih, const float* __restrict__ w_hh,
                            const float* __restrict__ b_ih, const float* __restrict__ b_hh) {
    int idx = blockIdx.x * blockDim.x + threadIdx.x;
    if (idx < NG * KDIM) {
        int r = idx >> 8;
        int k = idx & 255;
        int j = r >> 2, q = r & 3;
        int src = (q * HID + j) * KDIM + k;
        g_WihH[idx] = __float2bfloat16(w_ih[src]);
        g_WhhH[idx] = __float2bfloat16(w_hh[src]);
        if (k == 0) g_bias[r] = b_ih[q * HID + j] + b_hh[q * HID + j];
    }
    if (idx < PATHS) g_att_u[idx] = 0u;
    if (idx < 16) { g_cnt_g[idx] = 0u; g_gen_g[idx] = 0u; }
    if (idx == 16) g_done = 0u;
}

// ---------------- embedding gather + bf16 convert ----------------
__global__ void gather_kernel(const float* __restrict__ emb, const int* __restrict__ paths) {
    int idx = blockIdx.x * blockDim.x + threadIdx.x;  // over 32768*64 float4 units
    int m = idx >> 6;
    int ch = idx & 63;
    int p = m & 4095, t = m >> 12;
    int node = paths[p * LEN + t];
    float4 v = *(const float4*)(emb + (size_t)node * DIM + ch * 4);
    __nv_bfloat162* dst = (__nv_bfloat162*)(g_x + (size_t)m * DIM + ch * 4);
    dst[0] = __floats2bfloat162_rn(v.x, v.y);
    dst[1] = __floats2bfloat162_rn(v.z, v.w);
}

// ---------------- one K=256 GEMM part: acc += src @ W^T (8 chunks, self-contained) ----------
__device__ __forceinline__ void do_part(
    uint32_t sb, const __nv_bfloat16* src0, uint32_t woff,
    int tid, int wm, int wn,
    int a_row_off, int a_k_off, int b_row_off, int b_k_off,
    float (&acc)[2][8][4])
{
    const int arow = tid >> 1;
    const int aoff = (tid & 1) * 16;
    // prologue: chunks 0,1
    #pragma unroll
    for (int s = 0; s < 2; s++) {
        uint32_t dst = sb + s * R_ASTG + arow * (ROWSTR * 2) + aoff * 2;
        const __nv_bfloat16* src = src0 + arow * KDIM + s * BK + aoff;
        cp16(dst, src); cp16(dst + 16, src + 8);
        cp_commit();
    }
    #pragma unroll
    for (int kc = 0; kc < 8; kc++) {
        if (kc < 7) cp_wait<1>(); else cp_wait<0>();
        __syncthreads();

        if (kc + 2 < 8) {
            int s = kc + 2;
            uint32_t dst = sb + (s % 3) * R_ASTG + arow * (ROWSTR * 2) + aoff * 2;
            const __nv_bfloat16* src = src0 + arow * KDIM + s * BK + aoff;
            cp16(dst, src); cp16(dst + 16, src + 8);
            cp_commit();
        }

        const uint32_t Abase = sb + (kc % 3) * R_ASTG;
        const uint32_t Bbase = sb + woff;
        const int kT = kc * BK;

        #pragma unroll
        for (int s2 = 0; s2 < 2; s2++) {
            const int kb = s2 * 16;
            uint32_t afr[2][4], bfr[4][4];
            #pragma unroll
            for (int mt = 0; mt < 2; mt++) {
                int rb = wm * 32 + mt * 16;
                ldsm4(afr[mt], Abase + (rb + a_row_off) * (ROWSTR * 2) + (kb + a_k_off) * 2);
            }
            #pragma unroll
            for (int u = 0; u < 4; u++) {
                int cb = wn * 64 + u * 16;
                ldsm4(bfr[u], Bbase + (cb + b_row_off) * (RSTR_B * 2) + (kT + kb + b_k_off) * 2);
            }
            #pragma unroll
            for (int mt = 0; mt < 2; mt++)
                #pragma unroll
                for (int u = 0; u < 4; u++) {
                    mma_bf16(acc[mt][2 * u],     afr[mt], &bfr[u][0]);
                    mma_bf16(acc[mt][2 * u + 1], afr[mt], &bfr[u][2]);
                }
        }
    }
    __syncthreads();   // all ldsm of chunk 7 retired before stages are rewritten
}

// ---------------- fused LSTM: x-part of step t+1 overlapped with barrier wait ----------------
__global__ void __launch_bounds__(512, 1)
lstm_kernel() {
    extern __shared__ __nv_bfloat16 smem[];
    char* smc = (char*)smem;
    const uint32_t sb = (uint32_t)__cvta_generic_to_shared(smem);
    const int tid = threadIdx.x;
    const int mg = blockIdx.x >> 3;            // m-group (16 groups of 8 CTAs)
    const int m0 = mg * R_BM;
    const int n0 = (blockIdx.x & 7) * R_BN;

    const int warp = tid >> 5, lane = tid & 31;
    const int wm = warp >> 1, wn = warp & 1;     // 8 x 2 warps, warp tile 32 x 64
    const int g = lane >> 2, t4 = lane & 3;
    const int li = lane & 7;
    const int a_row_off = ((lane >> 3) & 1) * 8 + li;
    const int a_k_off = (lane >> 4) * 8;
    const int b_row_off = ((lane >> 4) & 1) * 8 + li;
    const int b_k_off = ((lane >> 3) & 1) * 8;

    // ---- persistent weight tiles: Wih + Whh rows n0..n0+127 (one cp group) ----
    #pragma unroll
    for (int kk = 0; kk < 8; kk++) {
        int idx = tid + kk * 512;
        int row = idx >> 5, ch = idx & 31;
        cp16(sb + W_OFF + row * (RSTR_B * 2) + ch * 16,
             g_WihH + (size_t)(n0 + row) * KDIM + ch * 8);
        cp16(sb + WHH_OFF + row * (RSTR_B * 2) + ch * 16,
             g_WhhH + (size_t)(n0 + row) * KDIM + ch * 8);
    }
    cp_commit();

    float* s_bias = (float*)(smc + BIAS_OFF);
    if (tid < 128) s_bias[tid] = g_bias[n0 + tid];

    const int odd = t4 & 1;
    const int rbase = wm * 32 + g + (odd ? 8 : 0);     // + mt*16
    const int jloc = wn * 16 + (t4 >> 1);              // + 2*nt (0..31)
    __nv_bfloat16* s_h = smem + H_OFF / 2;

    float creg[16];
    #pragma unroll
    for (int i = 0; i < 16; i++) creg[i] = 0.0f;       // c_{-1} = 0

    float acc[2][8][4];
    #pragma unroll
    for (int a = 0; a < 2; a++)
        #pragma unroll
        for (int b = 0; b < 8; b++)
            #pragma unroll
            for (int c = 0; c < 4; c++) acc[a][b][c] = 0.0f;

    // x-part of step 0 (weights group retired by first wait inside)
    do_part(sb, g_x + (size_t)m0 * KDIM, W_OFF,
            tid, wm, wn, a_row_off, a_k_off, b_row_off, b_k_off, acc);

    for (int t = 0; t < LEN; t++) {
        // ---- h-part: wait for h(t-1), then acc += h @ Whh^T ----
        if (t > 0) {
            if (tid == 0) {
                while (g_gen_g[mg] < (unsigned)t) { }
                __threadfence();
            }
            __syncthreads();
            do_part(sb, g_hbufH[(t + 1) & 1] + (size_t)m0 * KDIM, WHH_OFF,
                    tid, wm, wn, a_row_off, a_k_off, b_row_off, b_k_off, acc);
        }

        // ---- fused LSTM cell epilogue (registers + bias, shfl-pair quads) ----
        #pragma unroll
        for (int mt = 0; mt < 2; mt++) {
            float hmax = -1e30f;
            #pragma unroll
            for (int nt = 0; nt < 8; nt++) {
                int cl = wn * 64 + nt * 8 + 2 * t4;          // local col of v0
                float b0 = s_bias[cl], b1 = s_bias[cl + 1];
                float v0 = acc[mt][nt][0] + b0;
                float v1 = acc[mt][nt][1] + b1;
                float v2 = acc[mt][nt][2] + b0;
                float v3 = acc[mt][nt][3] + b1;
                float r0 = __shfl_xor_sync(0xffffffffu, v0, 1);
                float r1 = __shfl_xor_sync(0xffffffffu, v1, 1);
                float r2 = __shfl_xor_sync(0xffffffffu, v2, 1);
                float r3 = __shfl_xor_sync(0xffffffffu, v3, 1);
                float qi, qf, qg, qo;
                if (!odd) { qi = v0; qf = v1; qg = r0; qo = r1; }
                else      { qi = r2; qf = r3; qg = v2; qo = v3; }
                float ig = sigf(qi);
                float fg = sigf(qf);
                float gg = tanh_fast(qg);
                float og = sigf(qo);
                float c = fg * creg[mt * 8 + nt] + ig * gg;
                creg[mt * 8 + nt] = c;
                float h = og * tanh_fast(c);
                s_h[(rbase + mt * 16) * ROWSTR + jloc + 2 * nt] = __float2bfloat16(h);
                hmax = fmaxf(hmax, h);
            }
            if (t == LEN - 1) {
                hmax = fmaxf(hmax, __shfl_xor_sync(0xffffffffu, hmax, 2));
                if (t4 < 2) atomicMax(&g_att_u[m0 + rbase + mt * 16], enc_f(hmax));
            }
        }

        // ---- coalesced h store from staging ----
        __syncthreads();
        {
            __nv_bfloat16* hout = g_hbufH[t & 1];
            int row = tid >> 1, part = tid & 1;
            const uint4* srcq = (const uint4*)(s_h + row * ROWSTR + part * 16);
            uint4* dstq = (uint4*)&hout[(size_t)(m0 + row) * HID + (n0 >> 2) + part * 16];
            dstq[0] = srcq[0];
            dstq[1] = srcq[1];
        }

        if (t + 1 < LEN) {
            // ---- arrive (non-blocking) ----
            __threadfence();
            __syncthreads();
            if (tid == 0) {
                unsigned old = atomicAdd(&g_cnt_g[mg], 1u);
                if (old == (unsigned)((t + 1) * 8 - 1)) {
                    __threadfence();
                    g_gen_g[mg] = (unsigned)(t + 1);
                }
            }
            // ---- x-part of step t+1 (barrier-independent; overlaps others' stragglers) ----
            #pragma unroll
            for (int a = 0; a < 2; a++)
                #pragma unroll
                for (int b = 0; b < 8; b++)
                    #pragma unroll
                    for (int c = 0; c < 4; c++) acc[a][b][c] = 0.0f;
            do_part(sb, g_x + ((size_t)(t + 1) * PATHS + m0) * KDIM, W_OFF,
                    tid, wm, wn, a_row_off, a_k_off, b_row_off, b_k_off, acc);
        }
    }
}

// ---------------- softmax over 4096 paths (1 block); also zeroes g_pe ----------------
__global__ void softmax_kernel() {
    __shared__ float red[32];
    __shared__ float bval;
    int tid = threadIdx.x;        // 1024 threads
    if (tid < HID) g_pe[tid] = 0.0f;
    float l[4];
    float m = -1e30f;
    #pragma unroll
    for (int i = 0; i < 4; i++) { l[i] = dec_f(g_att_u[tid * 4 + i]); m = fmaxf(m, l[i]); }
    #pragma unroll
    for (int o = 16; o; o >>= 1) m = fmaxf(m, __shfl_xor_sync(0xffffffffu, m, o));
    if ((tid & 31) == 0) red[tid >> 5] = m;
    __syncthreads();
    if (tid < 32) {
        float v = red[tid];
        #pragma unroll
        for (int o = 16; o; o >>= 1) v = fmaxf(v, __shfl_xor_sync(0xffffffffu, v, o));
        if (tid == 0) bval = v;
    }
    __syncthreads();
    float M = bval;
    float e[4], s = 0.0f;
    #pragma unroll
    for (int i = 0; i < 4; i++) { e[i] = __expf(l[i] - M); s += e[i]; }
    #pragma unroll
    for (int o = 16; o; o >>= 1) s += __shfl_xor_sync(0xffffffffu, s, o);
    if ((tid & 31) == 0) red[tid >> 5] = s;
    __syncthreads();
    if (tid < 32) {
        float v = red[tid];
        #pragma unroll
        for (int o = 16; o; o >>= 1) v += __shfl_xor_sync(0xffffffffu, v, o);
        if (tid == 0) bval = v;
    }
    __syncthreads();
    float inv = __fdividef(1.0f, bval);
    #pragma unroll
    for (int i = 0; i < 4; i++) g_att[tid * 4 + i] = e[i] * inv;
}

// ---------------- pathemb (coalesced, 32 blocks) + final in last block ----------------
__global__ void pathemb_kernel(const float* __restrict__ emb, const float* __restrict__ w_lin,
                               const float* __restrict__ b_lin, const int* __restrict__ user_id,
                               const int* __restrict__ item_id, float* __restrict__ out) {
    __shared__ float s_att[128];
    __shared__ float red[8];
    __shared__ int s_last;
    int tid = threadIdx.x;             // 256 threads; thread = hidden column
    int wid = tid >> 5, lane = tid & 31;
    int p0 = blockIdx.x * 128;

    if (tid < 128) s_att[tid] = g_att[p0 + tid];
    __syncthreads();

    // coalesced: each iteration, 256 threads read one full 512B h row
    const __nv_bfloat16* h = g_hbufH[1] + (size_t)p0 * HID;
    float acc = 0.0f;
    #pragma unroll 4
    for (int p = 0; p < 128; p++)
        acc += s_att[p] * __bfloat162float(h[p * HID + tid]);
    atomicAdd(&g_pe[tid], acc);

    __threadfence();
    __syncthreads();
    if (tid == 0) s_last = (atomicAdd(&g_done, 1u) == (unsigned)(gridDim.x - 1));
    __syncthreads();

    if (s_last) {
        __threadfence();   // acquire: all blocks' atomics visible
        int u = user_id[0], it = item_id[0];
        float a = w_lin[tid] * emb[(size_t)u * DIM + tid]
                + w_lin[256 + tid] * emb[(size_t)it * DIM + tid]
                + w_lin[512 + tid] * g_pe[tid];
        #pragma unroll
        for (int o = 16; o; o >>= 1) a += __shfl_xor_sync(0xffffffffu, a, o);
        if (lane == 0) red[wid] = a;
        __syncthreads();
        if (tid == 0) {
            float sm = 0.0f;
            #pragma unroll
            for (int k = 0; k < 8; k++) sm += red[k];
            out[0] = 1.0f / (1.0f + expf(-(sm + b_lin[0])));
        }
    }
}

// ---------------- host ----------------
extern "C" void kernel_launch(void* const* d_in, const int* in_sizes, int n_in,
                              void* d_out, int out_size) {
    const float* emb   = (const float*)d_in[0];
    const float* w_ih  = (const float*)d_in[1];
    const float* w_hh  = (const float*)d_in[2];
    const float* b_ih  = (const float*)d_in[3];
    const float* b_hh  = (const float*)d_in[4];
    const float* w_lin = (const float*)d_in[5];
    const float* b_lin = (const float*)d_in[6];
    const int* paths   = (const int*)d_in[7];
    const int* uid     = (const int*)d_in[8];
    const int* iid     = (const int*)d_in[9];
    float* out = (float*)d_out;

    cudaFuncSetAttribute(lstm_kernel, cudaFuncAttributeMaxDynamicSharedMemorySize, SMEM_LSTM);

    prep_kernel<<<(NG * KDIM) / 256, 256>>>(w_ih, w_hh, b_ih, b_hh);
    gather_kernel<<<(LEN * PATHS * 64) / 256, 256>>>(emb, paths);

    // ALL 8 LSTM steps in one persistent kernel; x-part of t+1 overlaps the inter-step barrier
    lstm_kernel<<<R_CTAS, 512, SMEM_LSTM>>>();

    softmax_kernel<<<1, 1024>>>();
    pathemb_kernel<<<PATHS / 128, 256>>>(emb, w_lin, b_lin, uid, iid, out);
}

// round 16
// speedup vs baseline: 2.9664x; 1.0106x over previous
#include <cuda_runtime.h>
#include <cuda_bf16.h>
#include <cstdint>
#include <math.h>

#define PATHS 4096
#define LEN 8
#define DIM 256
#define HID 256
#define NG 1024   // 4*HID
#define KDIM 256
#define BK 32            // halves per k-chunk
#define ROWSTR 40        // halves per A-stage / h-staging smem row (80B)

// ---- fused LSTM: 128 CTAs x 512 threads, BM=256 x BN=128, 1 CTA/SM ----
#define R_BM 256
#define R_BN 128
#define RSTR_B 264                            // halves per W row (528B)
#define R_ASTG (R_BM * ROWSTR * 2)            // 20480 B per A stage (3 stages)
#define W_OFF (3 * R_ASTG)                    // 61440: Wih tile
#define WHH_OFF (W_OFF + R_BN * RSTR_B * 2)   // 129024: Whh tile
#define H_OFF (WHH_OFF + R_BN * RSTR_B * 2)   // 196608: h staging (256 x 40 halves)
#define BIAS_OFF (H_OFF + R_BM * ROWSTR * 2)  // 217088: bias (128 floats)
#define SMEM_LSTM (BIAS_OFF + 512)            // 217600
#define R_CTAS 128

// ---------------- device scratch ----------------
__device__ __nv_bfloat16 g_x[(size_t)LEN * PATHS * DIM];    // 16 MB gathered+converted embeddings
__device__ __nv_bfloat16 g_WihH[NG * KDIM];                 // permuted bf16 w_ih (row 4j+q)
__device__ __nv_bfloat16 g_WhhH[NG * KDIM];                 // permuted bf16 w_hh
__device__ float g_bias[NG];
__device__ __nv_bfloat16 g_hbufH[2][PATHS * HID];
__device__ unsigned g_att_u[PATHS];                         // monotonic-encoded float max
__device__ float g_pe_part[32 * HID];                       // per-block pathemb partials
__device__ unsigned g_cnt_g[16];                            // per-m-group barrier arrivals
__device__ volatile unsigned g_gen_g[16];                   // per-m-group barrier generation
__device__ unsigned g_done;                                 // tail last-block counter

// ---------------- helpers ----------------
__device__ __forceinline__ void cp16(uint32_t smem_dst, const void* gmem_src) {
    asm volatile("cp.async.cg.shared.global [%0], [%1], 16;\n" :: "r"(smem_dst), "l"(gmem_src));
}
__device__ __forceinline__ void cp_commit() { asm volatile("cp.async.commit_group;\n"); }
template <int N>
__device__ __forceinline__ void cp_wait() { asm volatile("cp.async.wait_group %0;\n" :: "n"(N)); }

__device__ __forceinline__ void ldsm4(uint32_t* r, uint32_t saddr) {
    asm volatile("ldmatrix.sync.aligned.m8n8.x4.shared.b16 {%0,%1,%2,%3}, [%4];\n"
                 : "=r"(r[0]), "=r"(r[1]), "=r"(r[2]), "=r"(r[3]) : "r"(saddr));
}
__device__ __forceinline__ void mma_bf16(float* c, const uint32_t* a, const uint32_t* b) {
    asm volatile(
        "mma.sync.aligned.m16n8k16.row.col.f32.bf16.bf16.f32 "
        "{%0,%1,%2,%3},{%4,%5,%6,%7},{%8,%9},{%0,%1,%2,%3};\n"
        : "+f"(c[0]), "+f"(c[1]), "+f"(c[2]), "+f"(c[3])
        : "r"(a[0]), "r"(a[1]), "r"(a[2]), "r"(a[3]), "r"(b[0]), "r"(b[1]));
}
__device__ __forceinline__ float sigf(float x) { return __fdividef(1.0f, 1.0f + __expf(-x)); }
__device__ __forceinline__ float tanh_fast(float x) {
    float e = __expf(2.0f * x);
    return 1.0f - __fdividef(2.0f, e + 1.0f);
}
__device__ __forceinline__ unsigned enc_f(float f) {
    unsigned b = __float_as_uint(f);
    return (b & 0x80000000u) ? ~b : (b | 0x80000000u);
}
__device__ __forceinline__ float dec_f(unsigned u) {
    unsigned b = (u & 0x80000000u) ? (u ^ 0x80000000u) : ~u;
    return __uint_as_float(b);
}

// ---------------- setup: embedding gather + weight permute + state reset (fused) ----------
__global__ void setup_kernel(const float* __restrict__ emb, const int* __restrict__ paths,
                             const float* __restrict__ w_ih, const float* __restrict__ w_hh,
                             const float* __restrict__ b_ih, const float* __restrict__ b_hh) {
    int idx = blockIdx.x * blockDim.x + threadIdx.x;  // over 32768*64 float4 units

    // gather + bf16 convert
    int m = idx >> 6;
    int ch = idx & 63;
    int p = m & 4095, t = m >> 12;
    int node = paths[p * LEN + t];
    float4 v = *(const float4*)(emb + (size_t)node * DIM + ch * 4);
    __nv_bfloat162* dst = (__nv_bfloat162*)(g_x + (size_t)m * DIM + ch * 4);
    dst[0] = __floats2bfloat162_rn(v.x, v.y);
    dst[1] = __floats2bfloat162_rn(v.z, v.w);

    // weight permute + bf16 (first NG*KDIM threads)
    if (idx < NG * KDIM) {
        int r = idx >> 8;
        int k = idx & 255;
        int j = r >> 2, q = r & 3;
        int src = (q * HID + j) * KDIM + k;
        g_WihH[idx] = __float2bfloat16(w_ih[src]);
        g_WhhH[idx] = __float2bfloat16(w_hh[src]);
        if (k == 0) g_bias[r] = b_ih[q * HID + j] + b_hh[q * HID + j];
    }
    if (idx < PATHS) g_att_u[idx] = 0u;
    if (idx < 16) { g_cnt_g[idx] = 0u; g_gen_g[idx] = 0u; }
    if (idx == 16) g_done = 0u;
}

// ---------------- one K=256 GEMM part: acc += src @ W^T (8 chunks, self-contained) ----------
__device__ __forceinline__ void do_part(
    uint32_t sb, const __nv_bfloat16* src0, uint32_t woff,
    int tid, int wm, int wn,
    int a_row_off, int a_k_off, int b_row_off, int b_k_off,
    float (&acc)[2][8][4])
{
    const int arow = tid >> 1;
    const int aoff = (tid & 1) * 16;
    // prologue: chunks 0,1
    #pragma unroll
    for (int s = 0; s < 2; s++) {
        uint32_t dst = sb + s * R_ASTG + arow * (ROWSTR * 2) + aoff * 2;
        const __nv_bfloat16* src = src0 + arow * KDIM + s * BK + aoff;
        cp16(dst, src); cp16(dst + 16, src + 8);
        cp_commit();
    }
    #pragma unroll
    for (int kc = 0; kc < 8; kc++) {
        if (kc < 7) cp_wait<1>(); else cp_wait<0>();
        __syncthreads();

        if (kc + 2 < 8) {
            int s = kc + 2;
            uint32_t dst = sb + (s % 3) * R_ASTG + arow * (ROWSTR * 2) + aoff * 2;
            const __nv_bfloat16* src = src0 + arow * KDIM + s * BK + aoff;
            cp16(dst, src); cp16(dst + 16, src + 8);
            cp_commit();
        }

        const uint32_t Abase = sb + (kc % 3) * R_ASTG;
        const uint32_t Bbase = sb + woff;
        const int kT = kc * BK;

        #pragma unroll
        for (int s2 = 0; s2 < 2; s2++) {
            const int kb = s2 * 16;
            uint32_t afr[2][4], bfr[4][4];
            #pragma unroll
            for (int mt = 0; mt < 2; mt++) {
                int rb = wm * 32 + mt * 16;
                ldsm4(afr[mt], Abase + (rb + a_row_off) * (ROWSTR * 2) + (kb + a_k_off) * 2);
            }
            #pragma unroll
            for (int u = 0; u < 4; u++) {
                int cb = wn * 64 + u * 16;
                ldsm4(bfr[u], Bbase + (cb + b_row_off) * (RSTR_B * 2) + (kT + kb + b_k_off) * 2);
            }
            #pragma unroll
            for (int mt = 0; mt < 2; mt++)
                #pragma unroll
                for (int u = 0; u < 4; u++) {
                    mma_bf16(acc[mt][2 * u],     afr[mt], &bfr[u][0]);
                    mma_bf16(acc[mt][2 * u + 1], afr[mt], &bfr[u][2]);
                }
        }
    }
    __syncthreads();   // all ldsm of chunk 7 retired before stages are rewritten
}

// ---------------- fused LSTM: x-part of step t+1 overlapped with barrier wait ----------------
__global__ void __launch_bounds__(512, 1)
lstm_kernel() {
    extern __shared__ __nv_bfloat16 smem[];
    char* smc = (char*)smem;
    const uint32_t sb = (uint32_t)__cvta_generic_to_shared(smem);
    const int tid = threadIdx.x;
    const int mg = blockIdx.x >> 3;            // m-group (16 groups of 8 CTAs)
    const int m0 = mg * R_BM;
    const int n0 = (blockIdx.x & 7) * R_BN;

    const int warp = tid >> 5, lane = tid & 31;
    const int wm = warp >> 1, wn = warp & 1;     // 8 x 2 warps, warp tile 32 x 64
    const int g = lane >> 2, t4 = lane & 3;
    const int li = lane & 7;
    const int a_row_off = ((lane >> 3) & 1) * 8 + li;
    const int a_k_off = (lane >> 4) * 8;
    const int b_row_off = ((lane >> 4) & 1) * 8 + li;
    const int b_k_off = ((lane >> 3) & 1) * 8;

    // ---- persistent weight tiles: Wih + Whh rows n0..n0+127 (one cp group) ----
    #pragma unroll
    for (int kk = 0; kk < 8; kk++) {
        int idx = tid + kk * 512;
        int row = idx >> 5, ch = idx & 31;
        cp16(sb + W_OFF + row * (RSTR_B * 2) + ch * 16,
             g_WihH + (size_t)(n0 + row) * KDIM + ch * 8);
        cp16(sb + WHH_OFF + row * (RSTR_B * 2) + ch * 16,
             g_WhhH + (size_t)(n0 + row) * KDIM + ch * 8);
    }
    cp_commit();

    float* s_bias = (float*)(smc + BIAS_OFF);
    if (tid < 128) s_bias[tid] = g_bias[n0 + tid];

    const int odd = t4 & 1;
    const int rbase = wm * 32 + g + (odd ? 8 : 0);     // + mt*16
    const int jloc = wn * 16 + (t4 >> 1);              // + 2*nt (0..31)
    __nv_bfloat16* s_h = smem + H_OFF / 2;

    float creg[16];
    #pragma unroll
    for (int i = 0; i < 16; i++) creg[i] = 0.0f;       // c_{-1} = 0

    float acc[2][8][4];
    #pragma unroll
    for (int a = 0; a < 2; a++)
        #pragma unroll
        for (int b = 0; b < 8; b++)
            #pragma unroll
            for (int c = 0; c < 4; c++) acc[a][b][c] = 0.0f;

    // x-part of step 0 (weights group retired by first wait inside)
    do_part(sb, g_x + (size_t)m0 * KDIM, W_OFF,
            tid, wm, wn, a_row_off, a_k_off, b_row_off, b_k_off, acc);

    for (int t = 0; t < LEN; t++) {
        // ---- h-part: wait for h(t-1), then acc += h @ Whh^T ----
        if (t > 0) {
            if (tid == 0) {
                while (g_gen_g[mg] < (unsigned)t) { }
                __threadfence();
            }
            __syncthreads();
            do_part(sb, g_hbufH[(t + 1) & 1] + (size_t)m0 * KDIM, WHH_OFF,
                    tid, wm, wn, a_row_off, a_k_off, b_row_off, b_k_off, acc);
        }

        // ---- fused LSTM cell epilogue (registers + bias, shfl-pair quads) ----
        #pragma unroll
        for (int mt = 0; mt < 2; mt++) {
            float hmax = -1e30f;
            #pragma unroll
            for (int nt = 0; nt < 8; nt++) {
                int cl = wn * 64 + nt * 8 + 2 * t4;          // local col of v0
                float b0 = s_bias[cl], b1 = s_bias[cl + 1];
                float v0 = acc[mt][nt][0] + b0;
                float v1 = acc[mt][nt][1] + b1;
                float v2 = acc[mt][nt][2] + b0;
                float v3 = acc[mt][nt][3] + b1;
                float r0 = __shfl_xor_sync(0xffffffffu, v0, 1);
                float r1 = __shfl_xor_sync(0xffffffffu, v1, 1);
                float r2 = __shfl_xor_sync(0xffffffffu, v2, 1);
                float r3 = __shfl_xor_sync(0xffffffffu, v3, 1);
                float qi, qf, qg, qo;
                if (!odd) { qi = v0; qf = v1; qg = r0; qo = r1; }
                else      { qi = r2; qf = r3; qg = v2; qo = v3; }
                float ig = sigf(qi);
                float fg = sigf(qf);
                float gg = tanh_fast(qg);
                float og = sigf(qo);
                float c = fg * creg[mt * 8 + nt] + ig * gg;
                creg[mt * 8 + nt] = c;
                float h = og * tanh_fast(c);
                s_h[(rbase + mt * 16) * ROWSTR + jloc + 2 * nt] = __float2bfloat16(h);
                hmax = fmaxf(hmax, h);
            }
            if (t == LEN - 1) {
                hmax = fmaxf(hmax, __shfl_xor_sync(0xffffffffu, hmax, 2));
                if (t4 < 2) atomicMax(&g_att_u[m0 + rbase + mt * 16], enc_f(hmax));
            }
        }

        // ---- coalesced h store from staging ----
        __syncthreads();
        {
            __nv_bfloat16* hout = g_hbufH[t & 1];
            int row = tid >> 1, part = tid & 1;
            const uint4* srcq = (const uint4*)(s_h + row * ROWSTR + part * 16);
            uint4* dstq = (uint4*)&hout[(size_t)(m0 + row) * HID + (n0 >> 2) + part * 16];
            dstq[0] = srcq[0];
            dstq[1] = srcq[1];
        }

        if (t + 1 < LEN) {
            // ---- arrive (non-blocking) ----
            __threadfence();
            __syncthreads();
            if (tid == 0) {
                unsigned old = atomicAdd(&g_cnt_g[mg], 1u);
                if (old == (unsigned)((t + 1) * 8 - 1)) {
                    __threadfence();
                    g_gen_g[mg] = (unsigned)(t + 1);
                }
            }
            // ---- x-part of step t+1 (barrier-independent; overlaps others' stragglers) ----
            #pragma unroll
            for (int a = 0; a < 2; a++)
                #pragma unroll
                for (int b = 0; b < 8; b++)
                    #pragma unroll
                    for (int c = 0; c < 4; c++) acc[a][b][c] = 0.0f;
            do_part(sb, g_x + ((size_t)(t + 1) * PATHS + m0) * KDIM, W_OFF,
                    tid, wm, wn, a_row_off, a_k_off, b_row_off, b_k_off, acc);
        }
    }
}

// ---------------- fused tail: softmax (redundant per block) + coalesced pathemb + final -----
__global__ void tail_kernel(const float* __restrict__ emb, const float* __restrict__ w_lin,
                            const float* __restrict__ b_lin, const int* __restrict__ user_id,
                            const int* __restrict__ item_id, float* __restrict__ out) {
    __shared__ float red[8];
    __shared__ float sval;
    __shared__ float s_att[128];
    __shared__ int s_last;
    int tid = threadIdx.x;             // 256 threads; thread = hidden column
    int wid = tid >> 5, lane = tid & 31;
    int p0 = blockIdx.x * 128;

    // global softmax stats (each block computes redundantly; 16 logits per thread)
    float l[16];
    float m = -1e30f;
    #pragma unroll
    for (int i = 0; i < 16; i++) {
        l[i] = dec_f(g_att_u[tid * 16 + i]);
        m = fmaxf(m, l[i]);
    }
    #pragma unroll
    for (int o = 16; o; o >>= 1) m = fmaxf(m, __shfl_xor_sync(0xffffffffu, m, o));
    if (lane == 0) red[wid] = m;
    __syncthreads();
    if (tid == 0) {
        float v = red[0];
        #pragma unroll
        for (int k = 1; k < 8; k++) v = fmaxf(v, red[k]);
        sval = v;
    }
    __syncthreads();
    float M = sval;
    float s = 0.0f;
    #pragma unroll
    for (int i = 0; i < 16; i++) s += __expf(l[i] - M);
    #pragma unroll
    for (int o = 16; o; o >>= 1) s += __shfl_xor_sync(0xffffffffu, s, o);
    if (lane == 0) red[wid] = s;
    __syncthreads();
    if (tid == 0) {
        float v = 0.0f;
        #pragma unroll
        for (int k = 0; k < 8; k++) v += red[k];
        sval = v;
    }
    __syncthreads();
    float inv = __fdividef(1.0f, sval);
    if (tid < 128) s_att[tid] = __expf(dec_f(g_att_u[p0 + tid]) - M) * inv;
    __syncthreads();

    // coalesced pathemb over this block's 128 paths
    const __nv_bfloat16* h = g_hbufH[1] + (size_t)p0 * HID;
    float acc = 0.0f;
    #pragma unroll 4
    for (int p = 0; p < 128; p++)
        acc += s_att[p] * __bfloat162float(h[p * HID + tid]);
    g_pe_part[blockIdx.x * HID + tid] = acc;

    __threadfence();
    __syncthreads();
    if (tid == 0) s_last = (atomicAdd(&g_done, 1u) == (unsigned)(gridDim.x - 1));
    __syncthreads();

    if (s_last) {
        __threadfence();   // acquire: all blocks' partials visible
        float pe = 0.0f;
        #pragma unroll
        for (int k = 0; k < 32; k++) pe += g_pe_part[k * HID + tid];
        int u = user_id[0], it = item_id[0];
        float a = w_lin[tid] * emb[(size_t)u * DIM + tid]
                + w_lin[256 + tid] * emb[(size_t)it * DIM + tid]
                + w_lin[512 + tid] * pe;
        #pragma unroll
        for (int o = 16; o; o >>= 1) a += __shfl_xor_sync(0xffffffffu, a, o);
        if (lane == 0) red[wid] = a;
        __syncthreads();
        if (tid == 0) {
            float sm = 0.0f;
            #pragma unroll
            for (int k = 0; k < 8; k++) sm += red[k];
            out[0] = 1.0f / (1.0f + expf(-(sm + b_lin[0])));
        }
    }
}

// ---------------- host ----------------
extern "C" void kernel_launch(void* const* d_in, const int* in_sizes, int n_in,
                              void* d_out, int out_size) {
    const float* emb   = (const float*)d_in[0];
    const float* w_ih  = (const float*)d_in[1];
    const float* w_hh  = (const float*)d_in[2];
    const float* b_ih  = (const float*)d_in[3];
    const float* b_hh  = (const float*)d_in[4];
    const float* w_lin = (const float*)d_in[5];
    const float* b_lin = (const float*)d_in[6];
    const int* paths   = (const int*)d_in[7];
    const int* uid     = (const int*)d_in[8];
    const int* iid     = (const int*)d_in[9];
    float* out = (float*)d_out;

    cudaFuncSetAttribute(lstm_kernel, cudaFuncAttributeMaxDynamicSharedMemorySize, SMEM_LSTM);

    // gather + weight permute + state reset, fused
    setup_kernel<<<(LEN * PATHS * 64) / 256, 256>>>(emb, paths, w_ih, w_hh, b_ih, b_hh);

    // ALL 8 LSTM steps in one persistent kernel; x-part of t+1 overlaps the inter-step barrier
    lstm_kernel<<<R_CTAS, 512, SMEM_LSTM>>>();

    // softmax + pathemb + final, fused
    tail_kernel<<<PATHS / 128, 256>>>(emb, w_lin, b_lin, uid, iid, out);
}